// round 1
// baseline (speedup 1.0000x reference)
#include <cuda_runtime.h>
#include <math.h>

// ---------------- problem constants ----------------
#define H_DIM 4096
#define NH 32
#define NKV 2
#define HD 128
#define ROT 64
#define BB 2
#define SS 2048
#define QKV_DIM ((NH + 2*NKV)*HD)   // 4608
#define TOK (BB*SS)                 // 4096

// scratch (allocation-free rule: device globals)
__device__ float g_qkv[(size_t)TOK * QKV_DIM];     // 75.5 MB
__device__ float g_ctx[(size_t)TOK * (NH*HD)];     // 67 MB

// ---------------- SGEMM: C[M,N] = A[M,K] @ B[K,N] (+bias) ----------------
#define BM 128
#define BN 128
#define BKK 16
#define TM 8
#define TN 8

__global__ __launch_bounds__(256, 1) void sgemm_kernel(
    const float* __restrict__ A, const float* __restrict__ B,
    const float* __restrict__ bias, float* __restrict__ C,
    int M, int N, int K)
{
    __shared__ float As[BKK][BM];
    __shared__ float Bs[BKK][BN];
    const int tid = threadIdx.x;
    const int bx = blockIdx.x, by = blockIdx.y;
    const float* Ab = A + (size_t)by * BM * K;
    const float* Bb = B + (size_t)bx * BN;
    const int tr = tid >> 4;          // 0..15
    const int tc = tid & 15;          // 0..15
    const int arow = tid >> 2;        // 0..63
    const int acol = (tid & 3) << 2;  // 0,4,8,12
    const int brow = tid >> 5;        // 0..7
    const int bcol = (tid & 31) << 2; // 0..124

    float acc[TM][TN];
    #pragma unroll
    for (int i = 0; i < TM; i++)
        #pragma unroll
        for (int j = 0; j < TN; j++) acc[i][j] = 0.f;

    for (int k0 = 0; k0 < K; k0 += BKK) {
        #pragma unroll
        for (int off = 0; off < BM; off += 64) {
            float4 v = *(const float4*)(Ab + (size_t)(arow + off) * K + k0 + acol);
            As[acol + 0][arow + off] = v.x;
            As[acol + 1][arow + off] = v.y;
            As[acol + 2][arow + off] = v.z;
            As[acol + 3][arow + off] = v.w;
        }
        #pragma unroll
        for (int off = 0; off < BKK; off += 8) {
            *(float4*)&Bs[brow + off][bcol] =
                *(const float4*)(Bb + (size_t)(k0 + brow + off) * N + bcol);
        }
        __syncthreads();
        #pragma unroll
        for (int k = 0; k < BKK; k++) {
            float4 a0 = *(const float4*)&As[k][tr * TM];
            float4 a1 = *(const float4*)&As[k][tr * TM + 4];
            float4 b0 = *(const float4*)&Bs[k][tc * TN];
            float4 b1 = *(const float4*)&Bs[k][tc * TN + 4];
            float rm[8] = {a0.x, a0.y, a0.z, a0.w, a1.x, a1.y, a1.z, a1.w};
            float rn[8] = {b0.x, b0.y, b0.z, b0.w, b1.x, b1.y, b1.z, b1.w};
            #pragma unroll
            for (int i = 0; i < TM; i++)
                #pragma unroll
                for (int j = 0; j < TN; j++)
                    acc[i][j] += rm[i] * rn[j];
        }
        __syncthreads();
    }

    float bv[TN];
    #pragma unroll
    for (int j = 0; j < TN; j++)
        bv[j] = bias ? bias[(size_t)bx * BN + tc * TN + j] : 0.f;

    #pragma unroll
    for (int i = 0; i < TM; i++) {
        size_t row = (size_t)by * BM + tr * TM + i;
        float* cp = C + row * N + (size_t)bx * BN + tc * TN;
        float4 o0, o1;
        o0.x = acc[i][0] + bv[0]; o0.y = acc[i][1] + bv[1];
        o0.z = acc[i][2] + bv[2]; o0.w = acc[i][3] + bv[3];
        o1.x = acc[i][4] + bv[4]; o1.y = acc[i][5] + bv[5];
        o1.z = acc[i][6] + bv[6]; o1.w = acc[i][7] + bv[7];
        *(float4*)cp = o0;
        *(float4*)(cp + 4) = o1;
    }
}

// ---------------- RoPE (GPT-J interleaved, first ROT dims of q & k heads) ----
__global__ void rope_kernel(float* __restrict__ qkv)
{
    int idx = blockIdx.x * blockDim.x + threadIdx.x;
    const int total = TOK * (NH + NKV) * (ROT / 2);
    if (idx >= total) return;
    int i  = idx & 31;                 // pair index 0..31
    int t2 = idx >> 5;
    int hh = t2 % (NH + NKV);          // q heads then k heads (contiguous)
    int t  = t2 / (NH + NKV);          // token
    int s  = t & (SS - 1);             // position = seq index (arange)
    int base = hh * HD;
    // match jax fp32: inv_freq fp32, freq = pos*inv_freq fp32, then accurate sin/cos
    float inv  = 1.0f / powf(10000.0f, (float)(2 * i) / (float)ROT);
    float freq = (float)s * inv;
    double fd = (double)freq;
    float c = (float)cos(fd), sn = (float)sin(fd);
    float* p = qkv + (size_t)t * QKV_DIM + base + 2 * i;
    float x1 = p[0], x2 = p[1];
    p[0] = x1 * c - x2 * sn;
    p[1] = x2 * c + x1 * sn;
}

// ---------------- flash attention, fp32, causal, GQA ----------------
#define BQ 64
#define BKT 64
#define QSTR 68   // padded row stride for transposed Q/K and for P

__global__ __launch_bounds__(256, 1) void flash_kernel(
    const float* __restrict__ qkv, float* __restrict__ ctx)
{
    extern __shared__ float sm[];
    float* Qs = sm;                    // [128][QSTR]  (d-major, transposed)
    float* Ks = Qs + HD * QSTR;        // [128][QSTR]
    float* Vs = Ks + HD * QSTR;        // [BKT][HD]
    float* Ps = Vs + BKT * HD;         // [BQ][QSTR]

    const int tid = threadIdx.x;
    const int qt = blockIdx.x;         // q tile 0..31
    const int h  = blockIdx.y;         // head 0..31
    const int b  = blockIdx.z;         // batch 0..1
    const int kvh = h / (NH / NKV);
    const int qbase = qt * BQ;

    const float* qp = qkv + (size_t)b * SS * QKV_DIM + h * HD;
    const float* kp = qkv + (size_t)b * SS * QKV_DIM + NH * HD + kvh * HD;
    const float* vp = qkv + (size_t)b * SS * QKV_DIM + (NH + NKV) * HD + kvh * HD;

    const int lr  = tid >> 2;          // 0..63: row for cooperative loads
    const int ld0 = (tid & 3) << 5;    // 0,32,64,96

    // load Q tile transposed: Qs[d][r]
    {
        const float* src = qp + (size_t)(qbase + lr) * QKV_DIM + ld0;
        #pragma unroll
        for (int dd = 0; dd < 32; dd += 4) {
            float4 v = *(const float4*)(src + dd);
            Qs[(ld0 + dd + 0) * QSTR + lr] = v.x;
            Qs[(ld0 + dd + 1) * QSTR + lr] = v.y;
            Qs[(ld0 + dd + 2) * QSTR + lr] = v.z;
            Qs[(ld0 + dd + 3) * QSTR + lr] = v.w;
        }
    }

    const int tr = tid >> 4;   // row group: rows tr*4 .. tr*4+3
    const int tc = tid & 15;   // col group

    float m_i[4], l_i[4];
    float o_acc[4][8];
    #pragma unroll
    for (int i = 0; i < 4; i++) {
        m_i[i] = -INFINITY;
        l_i[i] = 0.f;
        #pragma unroll
        for (int j = 0; j < 8; j++) o_acc[i][j] = 0.f;
    }
    const float scale = 0.08838834764831845f; // 1/sqrt(128)

    for (int kt = 0; kt <= qt; ++kt) {
        const int kbase = kt * BKT;
        // load K transposed + V straight
        {
            const float* srck = kp + (size_t)(kbase + lr) * QKV_DIM + ld0;
            const float* srcv = vp + (size_t)(kbase + lr) * QKV_DIM + ld0;
            #pragma unroll
            for (int dd = 0; dd < 32; dd += 4) {
                float4 v = *(const float4*)(srck + dd);
                Ks[(ld0 + dd + 0) * QSTR + lr] = v.x;
                Ks[(ld0 + dd + 1) * QSTR + lr] = v.y;
                Ks[(ld0 + dd + 2) * QSTR + lr] = v.z;
                Ks[(ld0 + dd + 3) * QSTR + lr] = v.w;
                *(float4*)&Vs[lr * HD + ld0 + dd] = *(const float4*)(srcv + dd);
            }
        }
        __syncthreads();

        // S = Q K^T  (4x4 micro-tile per thread)
        float sacc[4][4];
        #pragma unroll
        for (int i = 0; i < 4; i++)
            #pragma unroll
            for (int j = 0; j < 4; j++) sacc[i][j] = 0.f;
        for (int d = 0; d < HD; ++d) {
            float4 rq = *(const float4*)&Qs[d * QSTR + tr * 4];
            float4 rk = *(const float4*)&Ks[d * QSTR + tc * 4];
            float qv[4] = {rq.x, rq.y, rq.z, rq.w};
            float kv[4] = {rk.x, rk.y, rk.z, rk.w};
            #pragma unroll
            for (int i = 0; i < 4; i++)
                #pragma unroll
                for (int j = 0; j < 4; j++)
                    sacc[i][j] += qv[i] * kv[j];
        }
        // scale + causal mask
        #pragma unroll
        for (int i = 0; i < 4; i++) {
            int qg = qbase + tr * 4 + i;
            #pragma unroll
            for (int j = 0; j < 4; j++) {
                int kg = kbase + tc * 4 + j;
                sacc[i][j] = (kg <= qg) ? sacc[i][j] * scale : -INFINITY;
            }
        }
        // online softmax, row stats replicated across the 16 threads of a row group
        #pragma unroll
        for (int i = 0; i < 4; i++) {
            float lm = fmaxf(fmaxf(sacc[i][0], sacc[i][1]),
                             fmaxf(sacc[i][2], sacc[i][3]));
            #pragma unroll
            for (int off = 8; off > 0; off >>= 1)
                lm = fmaxf(lm, __shfl_xor_sync(0xffffffffu, lm, off, 16));
            float nm = fmaxf(m_i[i], lm);
            float ls = 0.f;
            #pragma unroll
            for (int j = 0; j < 4; j++) {
                float p = expf(sacc[i][j] - nm);
                sacc[i][j] = p;
                ls += p;
            }
            #pragma unroll
            for (int off = 8; off > 0; off >>= 1)
                ls += __shfl_xor_sync(0xffffffffu, ls, off, 16);
            float alpha = expf(m_i[i] - nm);
            l_i[i] = l_i[i] * alpha + ls;
            m_i[i] = nm;
            #pragma unroll
            for (int j = 0; j < 8; j++) o_acc[i][j] *= alpha;
            float4 pw;
            pw.x = sacc[i][0]; pw.y = sacc[i][1];
            pw.z = sacc[i][2]; pw.w = sacc[i][3];
            *(float4*)&Ps[(tr * 4 + i) * QSTR + tc * 4] = pw;
        }
        __syncthreads();

        // O += P @ V  (rows tr*4+i, cols tc*8..tc*8+7)
        for (int kk = 0; kk < BKT; ++kk) {
            float rp[4];
            #pragma unroll
            for (int i = 0; i < 4; i++) rp[i] = Ps[(tr * 4 + i) * QSTR + kk];
            float4 v0 = *(const float4*)&Vs[kk * HD + tc * 8];
            float4 v1 = *(const float4*)&Vs[kk * HD + tc * 8 + 4];
            float rv[8] = {v0.x, v0.y, v0.z, v0.w, v1.x, v1.y, v1.z, v1.w};
            #pragma unroll
            for (int i = 0; i < 4; i++)
                #pragma unroll
                for (int j = 0; j < 8; j++)
                    o_acc[i][j] += rp[i] * rv[j];
        }
        __syncthreads();
    }

    // epilogue: O / l -> ctx[b, s, h*HD + d]
    #pragma unroll
    for (int i = 0; i < 4; i++) {
        float inv_l = 1.0f / l_i[i];
        size_t row = (size_t)b * SS + qbase + tr * 4 + i;
        float* op = ctx + row * (NH * HD) + h * HD + tc * 8;
        float4 o0, o1;
        o0.x = o_acc[i][0] * inv_l; o0.y = o_acc[i][1] * inv_l;
        o0.z = o_acc[i][2] * inv_l; o0.w = o_acc[i][3] * inv_l;
        o1.x = o_acc[i][4] * inv_l; o1.y = o_acc[i][5] * inv_l;
        o1.z = o_acc[i][6] * inv_l; o1.w = o_acc[i][7] * inv_l;
        *(float4*)op = o0;
        *(float4*)(op + 4) = o1;
    }
}

// ---------------- launcher ----------------
extern "C" void kernel_launch(void* const* d_in, const int* in_sizes, int n_in,
                              void* d_out, int out_size)
{
    const float* hidden = (const float*)d_in[0];
    // d_in[1] = position_ids (= broadcast arange; positions derived from seq index)
    const float* Wqkv = (const float*)d_in[2];
    const float* bqkv = (const float*)d_in[3];
    const float* Wo   = (const float*)d_in[4];
    float* out = (float*)d_out;

    float *qkv, *ctx;
    cudaGetSymbolAddress((void**)&qkv, g_qkv);
    cudaGetSymbolAddress((void**)&ctx, g_ctx);

    // 1) QKV GEMM + bias
    {
        dim3 grid(QKV_DIM / BN, TOK / BM);
        sgemm_kernel<<<grid, 256>>>(hidden, Wqkv, bqkv, qkv, TOK, QKV_DIM, H_DIM);
    }
    // 2) RoPE in-place on q & k heads
    {
        int total = TOK * (NH + NKV) * (ROT / 2);
        rope_kernel<<<(total + 255) / 256, 256>>>(qkv);
    }
    // 3) flash attention
    {
        const int smem = (HD * QSTR * 2 + BKT * HD + BQ * QSTR) * (int)sizeof(float);
        cudaFuncSetAttribute(flash_kernel,
                             cudaFuncAttributeMaxDynamicSharedMemorySize, smem);
        dim3 grid(SS / BQ, NH, BB);
        flash_kernel<<<grid, 256, smem>>>(qkv, ctx);
    }
    // 4) output GEMM
    {
        dim3 grid(H_DIM / BN, TOK / BM);
        sgemm_kernel<<<grid, 256>>>(ctx, Wo, nullptr, out, TOK, H_DIM, H_DIM);
    }
}

// round 4
// speedup vs baseline: 1.6914x; 1.6914x over previous
#include <cuda_runtime.h>
#include <cuda_bf16.h>
#include <math.h>
#include <stdint.h>

// ---------------- problem constants ----------------
#define H_DIM 4096
#define NH 32
#define NKV 2
#define HD 128
#define ROT 64
#define BB 2
#define SS 2048
#define QKV_DIM ((NH + 2*NKV)*HD)   // 4608
#define TOK (BB*SS)                 // 4096

// scratch (allocation-free rule: device globals)
__device__ float g_qkv[(size_t)TOK * QKV_DIM];
__device__ float g_ctx[(size_t)TOK * (NH*HD)];
__device__ __nv_bfloat16 g_Wq_h[(size_t)QKV_DIM * H_DIM];
__device__ __nv_bfloat16 g_Wq_l[(size_t)QKV_DIM * H_DIM];
__device__ __nv_bfloat16 g_Wo_h[(size_t)H_DIM * H_DIM];
__device__ __nv_bfloat16 g_Wo_l[(size_t)H_DIM * H_DIM];
__device__ __nv_bfloat16 g_A_h[(size_t)TOK * H_DIM];
__device__ __nv_bfloat16 g_A_l[(size_t)TOK * H_DIM];

// ---------------- PTX helpers (arch-generic: HMMA / ldmatrix / cp.async) ----
__device__ __forceinline__ uint32_t smem_u32(const void* p) {
    uint32_t a;
    asm("{ .reg .u64 t; cvta.to.shared.u64 t, %1; cvt.u32.u64 %0, t; }"
        : "=r"(a) : "l"(p));
    return a;
}
__device__ __forceinline__ void ldsm4(uint32_t* r, uint32_t addr) {
    asm volatile("ldmatrix.sync.aligned.m8n8.x4.shared.b16 {%0,%1,%2,%3}, [%4];"
                 : "=r"(r[0]), "=r"(r[1]), "=r"(r[2]), "=r"(r[3]) : "r"(addr));
}
__device__ __forceinline__ void mma_bf16(float* d, const uint32_t* a,
                                         uint32_t b0, uint32_t b1) {
    asm volatile("mma.sync.aligned.m16n8k16.row.col.f32.bf16.bf16.f32 "
                 "{%0,%1,%2,%3}, {%4,%5,%6,%7}, {%8,%9}, {%0,%1,%2,%3};"
                 : "+f"(d[0]), "+f"(d[1]), "+f"(d[2]), "+f"(d[3])
                 : "r"(a[0]), "r"(a[1]), "r"(a[2]), "r"(a[3]), "r"(b0), "r"(b1));
}
#define CP_ASYNC16(dst, src) \
    asm volatile("cp.async.cg.shared.global [%0], [%1], 16;" :: "r"(dst), "l"(src))
#define CP_COMMIT() asm volatile("cp.async.commit_group;" ::: "memory")
#define CP_WAIT1() asm volatile("cp.async.wait_group 1;" ::: "memory")
#define CP_WAIT0() asm volatile("cp.async.wait_group 0;" ::: "memory")

// ---------------- conversion kernels ----------------
__global__ void split_kernel(const float4* __restrict__ x,
                             __nv_bfloat162* __restrict__ h,
                             __nv_bfloat162* __restrict__ l, int n4)
{
    int i = blockIdx.x * blockDim.x + threadIdx.x;
    if (i >= n4) return;
    float4 v = x[i];
    __nv_bfloat16 h0 = __float2bfloat16(v.x), h1 = __float2bfloat16(v.y);
    __nv_bfloat16 h2 = __float2bfloat16(v.z), h3 = __float2bfloat16(v.w);
    float r0 = v.x - __bfloat162float(h0), r1 = v.y - __bfloat162float(h1);
    float r2 = v.z - __bfloat162float(h2), r3 = v.w - __bfloat162float(h3);
    h[2*i]   = __nv_bfloat162(h0, h1);
    h[2*i+1] = __nv_bfloat162(h2, h3);
    l[2*i]   = __nv_bfloat162(__float2bfloat16(r0), __float2bfloat16(r1));
    l[2*i+1] = __nv_bfloat162(__float2bfloat16(r2), __float2bfloat16(r3));
}

// W [K][N] row-major -> Th/Tl [N][K] bf16 (hi/lo split)
__global__ void transpose_split_kernel(const float* __restrict__ W,
                                       __nv_bfloat16* __restrict__ Th,
                                       __nv_bfloat16* __restrict__ Tl, int K, int N)
{
    __shared__ float t[32][33];
    int n0 = blockIdx.x * 32, k0 = blockIdx.y * 32;
    int tx = threadIdx.x & 31, g = threadIdx.x >> 5;
    #pragma unroll
    for (int j = 0; j < 4; j++) {
        int ky = g * 4 + j;
        t[ky][tx] = W[(size_t)(k0 + ky) * N + n0 + tx];
    }
    __syncthreads();
    #pragma unroll
    for (int j = 0; j < 4; j++) {
        int ny = g * 4 + j;
        float v = t[tx][ny];
        __nv_bfloat16 h = __float2bfloat16(v);
        float r = v - __bfloat162float(h);
        Th[(size_t)(n0 + ny) * K + k0 + tx] = h;
        Tl[(size_t)(n0 + ny) * K + k0 + tx] = __float2bfloat16(r);
    }
}

// ---------------- HMMA GEMM: C[M,N] = A[M,K] @ B[N,K]^T (+bias) --------------
// bf16 hi/lo split: C = AhBh + AhBl + AlBh (fp32 accum)
#define BMg 128
#define BNg 128
#define BKg 32
#define ROWB 80            // padded row bytes (32 bf16 = 64B data + 16B pad)
#define TSZ (128*ROWB)     // 10240 B per tensor per stage
#define STGSZ (4*TSZ)      // 40960 B per stage (Ah, Al, Bh, Bl)
#define GSMEM (2*STGSZ)    // 81920 B (2 stages)

__global__ __launch_bounds__(256, 2) void gemm_tc_kernel(
    const __nv_bfloat16* __restrict__ Ah, const __nv_bfloat16* __restrict__ Al,
    const __nv_bfloat16* __restrict__ Bh, const __nv_bfloat16* __restrict__ Bl,
    const float* __restrict__ bias, float* __restrict__ C,
    int M, int N, int K)
{
    extern __shared__ char smem[];
    const uint32_t sb = smem_u32(smem);
    const int tid = threadIdx.x;
    const int wid = tid >> 5;
    const int lane = tid & 31;
    const int m0 = blockIdx.y * BMg;
    const int n0 = blockIdx.x * BNg;
    const int NC = K / BKg;

    const int wm = (wid >> 2) * 64;  // warp m-offset (2 warp-rows)
    const int wn = (wid & 3) * 32;   // warp n-offset (4 warp-cols)

    // ldmatrix per-lane address components
    const int a_row = (lane & 7) + ((lane >> 3) & 1) * 8;
    const int a_kh  = (lane >> 4) * 8;                    // in halfwords
    const int b_row = (lane & 7) + ((lane >> 4) & 1) * 8;
    const int b_kh  = ((lane >> 3) & 1) * 8;

    float acc[4][4][4];
    #pragma unroll
    for (int i = 0; i < 4; i++)
        #pragma unroll
        for (int j = 0; j < 4; j++)
            #pragma unroll
            for (int q = 0; q < 4; q++) acc[i][j][q] = 0.f;

    // loader: 8 x 16B cp.async per thread per stage
    const int lr_lo = tid >> 2;        // 0..63
    const int lc    = tid & 3;         // 16B unit within 64B row
    auto issue_loads = [&](int c, int buf) {
        const int k0 = c * BKg;
        const uint32_t sbuf = sb + buf * STGSZ;
        #pragma unroll
        for (int i = 0; i < 8; i++) {
            const int tensor = i >> 1;
            const int r = ((i & 1) << 6) + lr_lo;
            const __nv_bfloat16* src;
            if (tensor == 0)      src = Ah + (size_t)(m0 + r) * K + k0 + lc * 8;
            else if (tensor == 1) src = Al + (size_t)(m0 + r) * K + k0 + lc * 8;
            else if (tensor == 2) src = Bh + (size_t)(n0 + r) * K + k0 + lc * 8;
            else                  src = Bl + (size_t)(n0 + r) * K + k0 + lc * 8;
            uint32_t dst = sbuf + tensor * TSZ + r * ROWB + lc * 16;
            CP_ASYNC16(dst, src);
        }
        CP_COMMIT();
    };

    auto compute = [&](int buf) {
        const uint32_t sbuf = sb + buf * STGSZ;
        #pragma unroll
        for (int ks = 0; ks < 2; ks++) {
            uint32_t brh[2][4], brl[2][4];
            #pragma unroll
            for (int g = 0; g < 2; g++) {
                uint32_t addr = sbuf + 2 * TSZ +
                    (wn + g * 16 + b_row) * ROWB + (ks * 16 + b_kh) * 2;
                ldsm4(brh[g], addr);
                ldsm4(brl[g], addr + TSZ);
            }
            #pragma unroll
            for (int mt = 0; mt < 4; mt++) {
                uint32_t ah[4], al[4];
                uint32_t addrA = sbuf +
                    (wm + mt * 16 + a_row) * ROWB + (ks * 16 + a_kh) * 2;
                ldsm4(ah, addrA);
                ldsm4(al, addrA + TSZ);
                #pragma unroll
                for (int g = 0; g < 2; g++) {
                    #pragma unroll
                    for (int h8 = 0; h8 < 2; h8++) {
                        const int nt = g * 2 + h8;
                        mma_bf16(acc[mt][nt], ah, brh[g][h8*2], brh[g][h8*2+1]);
                        mma_bf16(acc[mt][nt], ah, brl[g][h8*2], brl[g][h8*2+1]);
                        mma_bf16(acc[mt][nt], al, brh[g][h8*2], brh[g][h8*2+1]);
                    }
                }
            }
        }
    };

    issue_loads(0, 0);
    for (int c = 0; c < NC; ++c) {
        const int buf = c & 1;
        if (c + 1 < NC) {
            issue_loads(c + 1, buf ^ 1);
            CP_WAIT1();
        } else {
            CP_WAIT0();
        }
        __syncthreads();
        compute(buf);
        __syncthreads();
    }

    // epilogue
    #pragma unroll
    for (int mt = 0; mt < 4; mt++) {
        const int m = m0 + wm + mt * 16 + (lane >> 2);
        #pragma unroll
        for (int nt = 0; nt < 4; nt++) {
            const int n = n0 + wn + nt * 8 + (lane & 3) * 2;
            float b0 = 0.f, b1 = 0.f;
            if (bias) { b0 = bias[n]; b1 = bias[n + 1]; }
            float2 v0, v1;
            v0.x = acc[mt][nt][0] + b0; v0.y = acc[mt][nt][1] + b1;
            v1.x = acc[mt][nt][2] + b0; v1.y = acc[mt][nt][3] + b1;
            *(float2*)&C[(size_t)m * N + n] = v0;
            *(float2*)&C[(size_t)(m + 8) * N + n] = v1;
        }
    }
}

// ---------------- RoPE ----------------
__global__ void rope_kernel(float* __restrict__ qkv)
{
    int idx = blockIdx.x * blockDim.x + threadIdx.x;
    const int total = TOK * (NH + NKV) * (ROT / 2);
    if (idx >= total) return;
    int i  = idx & 31;
    int t2 = idx >> 5;
    int hh = t2 % (NH + NKV);
    int t  = t2 / (NH + NKV);
    int s  = t & (SS - 1);
    int base = hh * HD;
    float inv  = 1.0f / powf(10000.0f, (float)(2 * i) / (float)ROT);
    float freq = (float)s * inv;
    double fd = (double)freq;
    float c = (float)cos(fd), sn = (float)sin(fd);
    float* p = qkv + (size_t)t * QKV_DIM + base + 2 * i;
    float x1 = p[0], x2 = p[1];
    p[0] = x1 * c - x2 * sn;
    p[1] = x2 * c + x1 * sn;
}

// ---------------- flash attention, fp32, causal, GQA ----------------
#define BQ 64
#define BKT 64
#define QSTR 68

__global__ __launch_bounds__(256, 1) void flash_kernel(
    const float* __restrict__ qkv, float* __restrict__ ctx)
{
    extern __shared__ float sm[];
    float* Qs = sm;
    float* Ks = Qs + HD * QSTR;
    float* Vs = Ks + HD * QSTR;
    float* Ps = Vs + BKT * HD;

    const int tid = threadIdx.x;
    const int qt = blockIdx.x;
    const int h  = blockIdx.y;
    const int b  = blockIdx.z;
    const int kvh = h / (NH / NKV);
    const int qbase = qt * BQ;

    const float* qp = qkv + (size_t)b * SS * QKV_DIM + h * HD;
    const float* kp = qkv + (size_t)b * SS * QKV_DIM + NH * HD + kvh * HD;
    const float* vp = qkv + (size_t)b * SS * QKV_DIM + (NH + NKV) * HD + kvh * HD;

    const int lr  = tid >> 2;
    const int ld0 = (tid & 3) << 5;

    {
        const float* src = qp + (size_t)(qbase + lr) * QKV_DIM + ld0;
        #pragma unroll
        for (int dd = 0; dd < 32; dd += 4) {
            float4 v = *(const float4*)(src + dd);
            Qs[(ld0 + dd + 0) * QSTR + lr] = v.x;
            Qs[(ld0 + dd + 1) * QSTR + lr] = v.y;
            Qs[(ld0 + dd + 2) * QSTR + lr] = v.z;
            Qs[(ld0 + dd + 3) * QSTR + lr] = v.w;
        }
    }

    const int tr = tid >> 4;
    const int tc = tid & 15;

    float m_i[4], l_i[4];
    float o_acc[4][8];
    #pragma unroll
    for (int i = 0; i < 4; i++) {
        m_i[i] = -INFINITY;
        l_i[i] = 0.f;
        #pragma unroll
        for (int j = 0; j < 8; j++) o_acc[i][j] = 0.f;
    }
    const float scale = 0.08838834764831845f;

    for (int kt = 0; kt <= qt; ++kt) {
        const int kbase = kt * BKT;
        {
            const float* srck = kp + (size_t)(kbase + lr) * QKV_DIM + ld0;
            const float* srcv = vp + (size_t)(kbase + lr) * QKV_DIM + ld0;
            #pragma unroll
            for (int dd = 0; dd < 32; dd += 4) {
                float4 v = *(const float4*)(srck + dd);
                Ks[(ld0 + dd + 0) * QSTR + lr] = v.x;
                Ks[(ld0 + dd + 1) * QSTR + lr] = v.y;
                Ks[(ld0 + dd + 2) * QSTR + lr] = v.z;
                Ks[(ld0 + dd + 3) * QSTR + lr] = v.w;
                *(float4*)&Vs[lr * HD + ld0 + dd] = *(const float4*)(srcv + dd);
            }
        }
        __syncthreads();

        float sacc[4][4];
        #pragma unroll
        for (int i = 0; i < 4; i++)
            #pragma unroll
            for (int j = 0; j < 4; j++) sacc[i][j] = 0.f;
        for (int d = 0; d < HD; ++d) {
            float4 rq = *(const float4*)&Qs[d * QSTR + tr * 4];
            float4 rk = *(const float4*)&Ks[d * QSTR + tc * 4];
            float qv[4] = {rq.x, rq.y, rq.z, rq.w};
            float kv[4] = {rk.x, rk.y, rk.z, rk.w};
            #pragma unroll
            for (int i = 0; i < 4; i++)
                #pragma unroll
                for (int j = 0; j < 4; j++)
                    sacc[i][j] += qv[i] * kv[j];
        }
        #pragma unroll
        for (int i = 0; i < 4; i++) {
            int qg = qbase + tr * 4 + i;
            #pragma unroll
            for (int j = 0; j < 4; j++) {
                int kg = kbase + tc * 4 + j;
                sacc[i][j] = (kg <= qg) ? sacc[i][j] * scale : -INFINITY;
            }
        }
        #pragma unroll
        for (int i = 0; i < 4; i++) {
            float lm = fmaxf(fmaxf(sacc[i][0], sacc[i][1]),
                             fmaxf(sacc[i][2], sacc[i][3]));
            #pragma unroll
            for (int off = 8; off > 0; off >>= 1)
                lm = fmaxf(lm, __shfl_xor_sync(0xffffffffu, lm, off, 16));
            float nm = fmaxf(m_i[i], lm);
            float ls = 0.f;
            #pragma unroll
            for (int j = 0; j < 4; j++) {
                float p = expf(sacc[i][j] - nm);
                sacc[i][j] = p;
                ls += p;
            }
            #pragma unroll
            for (int off = 8; off > 0; off >>= 1)
                ls += __shfl_xor_sync(0xffffffffu, ls, off, 16);
            float alpha = expf(m_i[i] - nm);
            l_i[i] = l_i[i] * alpha + ls;
            m_i[i] = nm;
            #pragma unroll
            for (int j = 0; j < 8; j++) o_acc[i][j] *= alpha;
            float4 pw;
            pw.x = sacc[i][0]; pw.y = sacc[i][1];
            pw.z = sacc[i][2]; pw.w = sacc[i][3];
            *(float4*)&Ps[(tr * 4 + i) * QSTR + tc * 4] = pw;
        }
        __syncthreads();

        for (int kk = 0; kk < BKT; ++kk) {
            float rp[4];
            #pragma unroll
            for (int i = 0; i < 4; i++) rp[i] = Ps[(tr * 4 + i) * QSTR + kk];
            float4 v0 = *(const float4*)&Vs[kk * HD + tc * 8];
            float4 v1 = *(const float4*)&Vs[kk * HD + tc * 8 + 4];
            float rv[8] = {v0.x, v0.y, v0.z, v0.w, v1.x, v1.y, v1.z, v1.w};
            #pragma unroll
            for (int i = 0; i < 4; i++)
                #pragma unroll
                for (int j = 0; j < 8; j++)
                    o_acc[i][j] += rp[i] * rv[j];
        }
        __syncthreads();
    }

    #pragma unroll
    for (int i = 0; i < 4; i++) {
        float inv_l = 1.0f / l_i[i];
        size_t row = (size_t)b * SS + qbase + tr * 4 + i;
        float* op = ctx + row * (NH * HD) + h * HD + tc * 8;
        float4 o0, o1;
        o0.x = o_acc[i][0] * inv_l; o0.y = o_acc[i][1] * inv_l;
        o0.z = o_acc[i][2] * inv_l; o0.w = o_acc[i][3] * inv_l;
        o1.x = o_acc[i][4] * inv_l; o1.y = o_acc[i][5] * inv_l;
        o1.z = o_acc[i][6] * inv_l; o1.w = o_acc[i][7] * inv_l;
        *(float4*)op = o0;
        *(float4*)(op + 4) = o1;
    }
}

// ---------------- launcher ----------------
extern "C" void kernel_launch(void* const* d_in, const int* in_sizes, int n_in,
                              void* d_out, int out_size)
{
    const float* hidden = (const float*)d_in[0];
    const float* Wqkv = (const float*)d_in[2];
    const float* bqkv = (const float*)d_in[3];
    const float* Wo   = (const float*)d_in[4];
    float* out = (float*)d_out;

    float *qkv, *ctx;
    __nv_bfloat16 *wqh, *wql, *woh, *wol, *ah, *al;
    cudaGetSymbolAddress((void**)&qkv, g_qkv);
    cudaGetSymbolAddress((void**)&ctx, g_ctx);
    cudaGetSymbolAddress((void**)&wqh, g_Wq_h);
    cudaGetSymbolAddress((void**)&wql, g_Wq_l);
    cudaGetSymbolAddress((void**)&woh, g_Wo_h);
    cudaGetSymbolAddress((void**)&wol, g_Wo_l);
    cudaGetSymbolAddress((void**)&ah, g_A_h);
    cudaGetSymbolAddress((void**)&al, g_A_l);

    // weight transpose+split: W[K][N] -> [N][K] bf16 hi/lo
    {
        dim3 g1(QKV_DIM / 32, H_DIM / 32);
        transpose_split_kernel<<<g1, 256>>>(Wqkv, wqh, wql, H_DIM, QKV_DIM);
        dim3 g2(H_DIM / 32, H_DIM / 32);
        transpose_split_kernel<<<g2, 256>>>(Wo, woh, wol, H_DIM, H_DIM);
    }
    // hidden split
    {
        int n4 = TOK * H_DIM / 4;
        split_kernel<<<(n4 + 255) / 256, 256>>>((const float4*)hidden,
                                                (__nv_bfloat162*)ah, (__nv_bfloat162*)al, n4);
    }
    // QKV GEMM (HMMA) + bias
    {
        cudaFuncSetAttribute(gemm_tc_kernel,
                             cudaFuncAttributeMaxDynamicSharedMemorySize, GSMEM);
        dim3 grid(QKV_DIM / BNg, TOK / BMg);
        gemm_tc_kernel<<<grid, 256, GSMEM>>>(ah, al, wqh, wql, bqkv, qkv,
                                             TOK, QKV_DIM, H_DIM);
    }
    // RoPE
    {
        int total = TOK * (NH + NKV) * (ROT / 2);
        rope_kernel<<<(total + 255) / 256, 256>>>(qkv);
    }
    // flash attention
    {
        const int smem = (HD * QSTR * 2 + BKT * HD + BQ * QSTR) * (int)sizeof(float);
        cudaFuncSetAttribute(flash_kernel,
                             cudaFuncAttributeMaxDynamicSharedMemorySize, smem);
        dim3 grid(SS / BQ, NH, BB);
        flash_kernel<<<grid, 256, smem>>>(qkv, ctx);
    }
    // ctx split (reuse A buffers)
    {
        int n4 = TOK * H_DIM / 4;
        split_kernel<<<(n4 + 255) / 256, 256>>>((const float4*)ctx,
                                                (__nv_bfloat162*)ah, (__nv_bfloat162*)al, n4);
    }
    // output GEMM (HMMA)
    {
        dim3 grid(H_DIM / BNg, TOK / BMg);
        gemm_tc_kernel<<<grid, 256, GSMEM>>>(ah, al, woh, wol, nullptr, out,
                                             TOK, H_DIM, H_DIM);
    }
}

// round 5
// speedup vs baseline: 3.1770x; 1.8783x over previous
#include <cuda_runtime.h>
#include <cuda_bf16.h>
#include <math.h>
#include <stdint.h>

// ---------------- problem constants ----------------
#define H_DIM 4096
#define NH 32
#define NKV 2
#define HD 128
#define ROT 64
#define BB 2
#define SS 2048
#define QKV_DIM ((NH + 2*NKV)*HD)   // 4608
#define TOK (BB*SS)                 // 4096
#define NSLOT (NH + 2*NKV)          // 36

// scratch (allocation-free rule: device globals)
__device__ float g_qkv[(size_t)TOK * QKV_DIM];
__device__ __nv_bfloat16 g_Wq_h[(size_t)QKV_DIM * H_DIM];
__device__ __nv_bfloat16 g_Wq_l[(size_t)QKV_DIM * H_DIM];
__device__ __nv_bfloat16 g_Wo_h[(size_t)H_DIM * H_DIM];
__device__ __nv_bfloat16 g_Wo_l[(size_t)H_DIM * H_DIM];
__device__ __nv_bfloat16 g_A_h[(size_t)TOK * H_DIM];
__device__ __nv_bfloat16 g_A_l[(size_t)TOK * H_DIM];
__device__ __nv_bfloat16 g_Qh[(size_t)TOK * NH * HD];
__device__ __nv_bfloat16 g_Ql[(size_t)TOK * NH * HD];
__device__ __nv_bfloat16 g_Kh[(size_t)TOK * NKV * HD];
__device__ __nv_bfloat16 g_Kl[(size_t)TOK * NKV * HD];
__device__ __nv_bfloat16 g_Vth[(size_t)TOK * NKV * HD];
__device__ __nv_bfloat16 g_Vtl[(size_t)TOK * NKV * HD];
__device__ float2 g_rope[SS * (ROT/2)];

// ---------------- PTX helpers (arch-generic: HMMA / ldmatrix / cp.async) ----
__device__ __forceinline__ uint32_t smem_u32(const void* p) {
    uint32_t a;
    asm("{ .reg .u64 t; cvta.to.shared.u64 t, %1; cvt.u32.u64 %0, t; }"
        : "=r"(a) : "l"(p));
    return a;
}
__device__ __forceinline__ void ldsm4(uint32_t* r, uint32_t addr) {
    asm volatile("ldmatrix.sync.aligned.m8n8.x4.shared.b16 {%0,%1,%2,%3}, [%4];"
                 : "=r"(r[0]), "=r"(r[1]), "=r"(r[2]), "=r"(r[3]) : "r"(addr));
}
__device__ __forceinline__ void mma_bf16(float* d, const uint32_t* a,
                                         uint32_t b0, uint32_t b1) {
    asm volatile("mma.sync.aligned.m16n8k16.row.col.f32.bf16.bf16.f32 "
                 "{%0,%1,%2,%3}, {%4,%5,%6,%7}, {%8,%9}, {%0,%1,%2,%3};"
                 : "+f"(d[0]), "+f"(d[1]), "+f"(d[2]), "+f"(d[3])
                 : "r"(a[0]), "r"(a[1]), "r"(a[2]), "r"(a[3]), "r"(b0), "r"(b1));
}
__device__ __forceinline__ uint32_t pack_bf16f(float lo, float hi) {
    uint32_t r;
    asm("cvt.rn.bf16x2.f32 %0, %1, %2;" : "=r"(r) : "f"(hi), "f"(lo));
    return r;
}
__device__ __forceinline__ float bf_hi(float x) {
    return __bfloat162float(__float2bfloat16(x));
}
#define CP_ASYNC16(dst, src) \
    asm volatile("cp.async.cg.shared.global [%0], [%1], 16;" :: "r"(dst), "l"(src))
#define CP_COMMIT() asm volatile("cp.async.commit_group;" ::: "memory")
#define CP_WAIT1() asm volatile("cp.async.wait_group 1;" ::: "memory")
#define CP_WAIT0() asm volatile("cp.async.wait_group 0;" ::: "memory")

// ---------------- conversion kernels ----------------
__global__ void split_kernel(const float4* __restrict__ x,
                             __nv_bfloat162* __restrict__ h,
                             __nv_bfloat162* __restrict__ l, int n4)
{
    int i = blockIdx.x * blockDim.x + threadIdx.x;
    if (i >= n4) return;
    float4 v = x[i];
    __nv_bfloat16 h0 = __float2bfloat16(v.x), h1 = __float2bfloat16(v.y);
    __nv_bfloat16 h2 = __float2bfloat16(v.z), h3 = __float2bfloat16(v.w);
    float r0 = v.x - __bfloat162float(h0), r1 = v.y - __bfloat162float(h1);
    float r2 = v.z - __bfloat162float(h2), r3 = v.w - __bfloat162float(h3);
    h[2*i]   = __nv_bfloat162(h0, h1);
    h[2*i+1] = __nv_bfloat162(h2, h3);
    l[2*i]   = __nv_bfloat162(__float2bfloat16(r0), __float2bfloat16(r1));
    l[2*i+1] = __nv_bfloat162(__float2bfloat16(r2), __float2bfloat16(r3));
}

// W [K][N] row-major -> Th/Tl [N][K] bf16 (hi/lo split)
__global__ void transpose_split_kernel(const float* __restrict__ W,
                                       __nv_bfloat16* __restrict__ Th,
                                       __nv_bfloat16* __restrict__ Tl, int K, int N)
{
    __shared__ float t[32][33];
    int n0 = blockIdx.x * 32, k0 = blockIdx.y * 32;
    int tx = threadIdx.x & 31, g = threadIdx.x >> 5;
    #pragma unroll
    for (int j = 0; j < 4; j++) {
        int ky = g * 4 + j;
        t[ky][tx] = W[(size_t)(k0 + ky) * N + n0 + tx];
    }
    __syncthreads();
    #pragma unroll
    for (int j = 0; j < 4; j++) {
        int ny = g * 4 + j;
        float v = t[tx][ny];
        __nv_bfloat16 h = __float2bfloat16(v);
        float r = v - __bfloat162float(h);
        Th[(size_t)(n0 + ny) * K + k0 + tx] = h;
        Tl[(size_t)(n0 + ny) * K + k0 + tx] = __float2bfloat16(r);
    }
}

// rope cos/sin table (accurate double trig, matches jax fp32 rounding)
__global__ void rope_table_kernel(float2* __restrict__ tab)
{
    int idx = blockIdx.x * blockDim.x + threadIdx.x;
    if (idx >= SS * (ROT/2)) return;
    int s = idx >> 5, i = idx & 31;
    float inv  = 1.0f / powf(10000.0f, (float)(2 * i) / (float)ROT);
    float freq = (float)s * inv;
    double fd = (double)freq;
    tab[idx] = make_float2((float)cos(fd), (float)sin(fd));
}

// qkv fp32 -> rope + hi/lo bf16 split into Q, K, Vt buffers
__global__ void rope_split_kernel(
    const float* __restrict__ qkv, const float2* __restrict__ tab,
    __nv_bfloat16* __restrict__ Qh, __nv_bfloat16* __restrict__ Ql,
    __nv_bfloat16* __restrict__ Kh, __nv_bfloat16* __restrict__ Kl,
    __nv_bfloat16* __restrict__ Vth, __nv_bfloat16* __restrict__ Vtl)
{
    int idx = blockIdx.x * blockDim.x + threadIdx.x;
    if (idx >= TOK * NSLOT * (HD/2)) return;
    int ip   = idx & 63;             // d-pair index, d = 2*ip
    int rest = idx >> 6;
    int slot = rest % NSLOT;
    int t    = rest / NSLOT;
    int s = t & (SS - 1), b = t >> 11;
    const float* src = qkv + (size_t)t * QKV_DIM + slot * HD + 2 * ip;
    float x1 = src[0], x2 = src[1];
    if (slot < NH + NKV && ip < ROT/2) {
        float2 cs = tab[s * (ROT/2) + ip];
        float o1 = x1 * cs.x - x2 * cs.y;
        float o2 = x2 * cs.x + x1 * cs.y;
        x1 = o1; x2 = o2;
    }
    float h1 = bf_hi(x1), h2 = bf_hi(x2);
    float l1 = x1 - h1, l2 = x2 - h2;
    if (slot < NH) {
        size_t base = ((size_t)(b * NH + slot) * SS + s) * HD + 2 * ip;
        *(uint32_t*)&Qh[base] = pack_bf16f(h1, h2);
        *(uint32_t*)&Ql[base] = pack_bf16f(l1, l2);
    } else if (slot < NH + NKV) {
        int kv = slot - NH;
        size_t base = ((size_t)(b * NKV + kv) * SS + s) * HD + 2 * ip;
        *(uint32_t*)&Kh[base] = pack_bf16f(h1, h2);
        *(uint32_t*)&Kl[base] = pack_bf16f(l1, l2);
    } else {
        int kv = slot - NH - NKV;
        size_t base = ((size_t)(b * NKV + kv) * HD + 2 * ip) * SS + s;
        Vth[base]      = __float2bfloat16(h1);
        Vtl[base]      = __float2bfloat16(l1);
        Vth[base + SS] = __float2bfloat16(h2);
        Vtl[base + SS] = __float2bfloat16(l2);
    }
}

// ---------------- HMMA GEMM: C[M,N] = A[M,K] @ B[N,K]^T (+bias) --------------
#define BMg 128
#define BNg 128
#define BKg 32
#define ROWB 80
#define TSZ (128*ROWB)
#define STGSZ (4*TSZ)
#define GSMEM (2*STGSZ)

__global__ __launch_bounds__(256, 2) void gemm_tc_kernel(
    const __nv_bfloat16* __restrict__ Ah, const __nv_bfloat16* __restrict__ Al,
    const __nv_bfloat16* __restrict__ Bh, const __nv_bfloat16* __restrict__ Bl,
    const float* __restrict__ bias, float* __restrict__ C,
    int M, int N, int K)
{
    extern __shared__ char smem[];
    const uint32_t sb = smem_u32(smem);
    const int tid = threadIdx.x;
    const int wid = tid >> 5;
    const int lane = tid & 31;
    const int m0 = blockIdx.y * BMg;
    const int n0 = blockIdx.x * BNg;
    const int NC = K / BKg;

    const int wm = (wid >> 2) * 64;
    const int wn = (wid & 3) * 32;

    const int a_row = (lane & 7) + ((lane >> 3) & 1) * 8;
    const int a_kh  = (lane >> 4) * 8;
    const int b_row = (lane & 7) + ((lane >> 4) & 1) * 8;
    const int b_kh  = ((lane >> 3) & 1) * 8;

    float acc[4][4][4];
    #pragma unroll
    for (int i = 0; i < 4; i++)
        #pragma unroll
        for (int j = 0; j < 4; j++)
            #pragma unroll
            for (int q = 0; q < 4; q++) acc[i][j][q] = 0.f;

    const int lr_lo = tid >> 2;
    const int lc    = tid & 3;
    auto issue_loads = [&](int c, int buf) {
        const int k0 = c * BKg;
        const uint32_t sbuf = sb + buf * STGSZ;
        #pragma unroll
        for (int i = 0; i < 8; i++) {
            const int tensor = i >> 1;
            const int r = ((i & 1) << 6) + lr_lo;
            const __nv_bfloat16* src;
            if (tensor == 0)      src = Ah + (size_t)(m0 + r) * K + k0 + lc * 8;
            else if (tensor == 1) src = Al + (size_t)(m0 + r) * K + k0 + lc * 8;
            else if (tensor == 2) src = Bh + (size_t)(n0 + r) * K + k0 + lc * 8;
            else                  src = Bl + (size_t)(n0 + r) * K + k0 + lc * 8;
            uint32_t dst = sbuf + tensor * TSZ + r * ROWB + lc * 16;
            CP_ASYNC16(dst, src);
        }
        CP_COMMIT();
    };

    auto compute = [&](int buf) {
        const uint32_t sbuf = sb + buf * STGSZ;
        #pragma unroll
        for (int ks = 0; ks < 2; ks++) {
            uint32_t brh[2][4], brl[2][4];
            #pragma unroll
            for (int g = 0; g < 2; g++) {
                uint32_t addr = sbuf + 2 * TSZ +
                    (wn + g * 16 + b_row) * ROWB + (ks * 16 + b_kh) * 2;
                ldsm4(brh[g], addr);
                ldsm4(brl[g], addr + TSZ);
            }
            #pragma unroll
            for (int mt = 0; mt < 4; mt++) {
                uint32_t ah[4], al[4];
                uint32_t addrA = sbuf +
                    (wm + mt * 16 + a_row) * ROWB + (ks * 16 + a_kh) * 2;
                ldsm4(ah, addrA);
                ldsm4(al, addrA + TSZ);
                #pragma unroll
                for (int g = 0; g < 2; g++) {
                    #pragma unroll
                    for (int h8 = 0; h8 < 2; h8++) {
                        const int nt = g * 2 + h8;
                        mma_bf16(acc[mt][nt], ah, brh[g][h8*2], brh[g][h8*2+1]);
                        mma_bf16(acc[mt][nt], ah, brl[g][h8*2], brl[g][h8*2+1]);
                        mma_bf16(acc[mt][nt], al, brh[g][h8*2], brh[g][h8*2+1]);
                    }
                }
            }
        }
    };

    issue_loads(0, 0);
    for (int c = 0; c < NC; ++c) {
        const int buf = c & 1;
        if (c + 1 < NC) {
            issue_loads(c + 1, buf ^ 1);
            CP_WAIT1();
        } else {
            CP_WAIT0();
        }
        __syncthreads();
        compute(buf);
        __syncthreads();
    }

    #pragma unroll
    for (int mt = 0; mt < 4; mt++) {
        const int m = m0 + wm + mt * 16 + (lane >> 2);
        #pragma unroll
        for (int nt = 0; nt < 4; nt++) {
            const int n = n0 + wn + nt * 8 + (lane & 3) * 2;
            float b0 = 0.f, b1 = 0.f;
            if (bias) { b0 = bias[n]; b1 = bias[n + 1]; }
            float2 v0, v1;
            v0.x = acc[mt][nt][0] + b0; v0.y = acc[mt][nt][1] + b1;
            v1.x = acc[mt][nt][2] + b0; v1.y = acc[mt][nt][3] + b1;
            *(float2*)&C[(size_t)m * N + n] = v0;
            *(float2*)&C[(size_t)(m + 8) * N + n] = v1;
        }
    }
}

// ---------------- HMMA flash attention (bf16 hi/lo split) --------------------
#define AQ 128
#define AK 64
#define QR 272                 // Q/K smem row bytes (128 bf16 + 16B pad)
#define VR 144                 // Vt smem row bytes (64 bf16 + 16B pad)
#define SQH (AQ*QR)            // 34816
#define SKH (AK*QR)            // 17408
#define SVH (HD*VR)            // 18432
#define STGA (2*SKH + 2*SVH)   // 71680
#define ASMEM (2*SQH + 2*STGA) // 212992

__global__ __launch_bounds__(256, 1) void attn_kernel(
    const __nv_bfloat16* __restrict__ Qh_g, const __nv_bfloat16* __restrict__ Ql_g,
    const __nv_bfloat16* __restrict__ Kh_g, const __nv_bfloat16* __restrict__ Kl_g,
    const __nv_bfloat16* __restrict__ Vth_g, const __nv_bfloat16* __restrict__ Vtl_g,
    __nv_bfloat16* __restrict__ Oh_g, __nv_bfloat16* __restrict__ Ol_g)
{
    extern __shared__ char smem[];
    const uint32_t sb = smem_u32(smem);
    const int tid = threadIdx.x;
    const int wid = tid >> 5;
    const int lane = tid & 31;
    const int qt = blockIdx.x;
    const int h  = blockIdx.y;
    const int b  = blockIdx.z;
    const int kvh = h / (NH / NKV);
    const int qbase = qt * AQ;
    const int ktmax = 2 * qt + 1;

    const size_t qoff = ((size_t)(b * NH + h) * SS + qbase) * HD;
    const size_t koff = ((size_t)(b * NKV + kvh) * SS) * HD;
    const size_t voff = ((size_t)(b * NKV + kvh) * HD) * SS;

    const int a_row = (lane & 7) + ((lane >> 3) & 1) * 8;
    const int a_kh  = (lane >> 4) * 8;
    const int b_row = (lane & 7) + ((lane >> 4) & 1) * 8;
    const int b_kh  = ((lane >> 3) & 1) * 8;

    // ---- load Q once (plain ld/st, 16B chunks): 2048 chunks per tensor ----
    #pragma unroll
    for (int i = 0; i < 8; i++) {
        int flat = i * 256 + tid;
        int r = flat >> 4, u = flat & 15;
        *(uint4*)(smem + r * QR + u * 16) =
            *(const uint4*)(Qh_g + qoff + (size_t)r * HD + u * 8);
        *(uint4*)(smem + SQH + r * QR + u * 16) =
            *(const uint4*)(Ql_g + qoff + (size_t)r * HD + u * 8);
    }

    // ---- K/V stage loader (cp.async) ----
    auto issue_kv = [&](int kt, int buf) {
        const int kbase = kt * AK;
        const uint32_t st = sb + 2 * SQH + buf * STGA;
        #pragma unroll
        for (int i = 0; i < 8; i++) {   // K hi+lo: 2048 chunks
            int flat = i * 256 + tid;
            int tensor = flat >> 10, rem = flat & 1023;
            int r = rem >> 4, u = rem & 15;
            const __nv_bfloat16* src = (tensor ? Kl_g : Kh_g) +
                koff + (size_t)(kbase + r) * HD + u * 8;
            CP_ASYNC16(st + tensor * SKH + r * QR + u * 16, src);
        }
        #pragma unroll
        for (int i = 0; i < 8; i++) {   // Vt hi+lo: 2048 chunks
            int flat = i * 256 + tid;
            int tensor = flat >> 10, rem = flat & 1023;
            int r = rem >> 3, u = rem & 7;
            const __nv_bfloat16* src = (tensor ? Vtl_g : Vth_g) +
                voff + (size_t)r * SS + kbase + u * 8;
            CP_ASYNC16(st + 2 * SKH + tensor * SVH + r * VR + u * 16, src);
        }
        CP_COMMIT();
    };

    float oacc[16][4];
    #pragma unroll
    for (int i = 0; i < 16; i++)
        #pragma unroll
        for (int j = 0; j < 4; j++) oacc[i][j] = 0.f;
    float m0 = -INFINITY, m1 = -INFINITY, l0 = 0.f, l1 = 0.f;
    const float scale = 0.08838834764831845f;
    const int row0 = qbase + wid * 16 + (lane >> 2);
    const int row1 = row0 + 8;

    issue_kv(0, 0);

    for (int kt = 0; kt <= ktmax; ++kt) {
        const int buf = kt & 1;
        const int kbase = kt * AK;
        if (kt + 1 <= ktmax) { issue_kv(kt + 1, buf ^ 1); CP_WAIT1(); }
        else CP_WAIT0();
        __syncthreads();

        const uint32_t stk = sb + 2 * SQH + buf * STGA;
        const uint32_t stv = stk + 2 * SKH;

        // ---- S = Q K^T (hi/lo split) ----
        float sacc[8][4];
        #pragma unroll
        for (int i = 0; i < 8; i++)
            #pragma unroll
            for (int j = 0; j < 4; j++) sacc[i][j] = 0.f;
        #pragma unroll
        for (int ks = 0; ks < 8; ks++) {
            uint32_t bh[4][4], bl[4][4];
            #pragma unroll
            for (int g = 0; g < 4; g++) {
                uint32_t addr = stk + (g * 16 + b_row) * QR + (ks * 16 + b_kh) * 2;
                ldsm4(bh[g], addr);
                ldsm4(bl[g], addr + SKH);
            }
            uint32_t qa_h[4], qa_l[4];
            uint32_t addrA = sb + (wid * 16 + a_row) * QR + (ks * 16 + a_kh) * 2;
            ldsm4(qa_h, addrA);
            ldsm4(qa_l, addrA + SQH);
            #pragma unroll
            for (int g = 0; g < 4; g++) {
                #pragma unroll
                for (int h8 = 0; h8 < 2; h8++) {
                    const int nt = g * 2 + h8;
                    mma_bf16(sacc[nt], qa_h, bh[g][h8*2], bh[g][h8*2+1]);
                    mma_bf16(sacc[nt], qa_h, bl[g][h8*2], bl[g][h8*2+1]);
                    mma_bf16(sacc[nt], qa_l, bh[g][h8*2], bh[g][h8*2+1]);
                }
            }
        }

        // ---- scale + causal mask ----
        const bool need_mask = (kbase + AK - 1) > (qbase + wid * 16);
        #pragma unroll
        for (int nt = 0; nt < 8; nt++) {
            int c0 = kbase + nt * 8 + (lane & 3) * 2;
            #pragma unroll
            for (int j = 0; j < 4; j++) sacc[nt][j] *= scale;
            if (need_mask) {
                if (c0     > row0) sacc[nt][0] = -INFINITY;
                if (c0 + 1 > row0) sacc[nt][1] = -INFINITY;
                if (c0     > row1) sacc[nt][2] = -INFINITY;
                if (c0 + 1 > row1) sacc[nt][3] = -INFINITY;
            }
        }

        // ---- online softmax ----
        float mx0 = -INFINITY, mx1 = -INFINITY;
        #pragma unroll
        for (int nt = 0; nt < 8; nt++) {
            mx0 = fmaxf(mx0, fmaxf(sacc[nt][0], sacc[nt][1]));
            mx1 = fmaxf(mx1, fmaxf(sacc[nt][2], sacc[nt][3]));
        }
        #pragma unroll
        for (int off = 1; off <= 2; off <<= 1) {
            mx0 = fmaxf(mx0, __shfl_xor_sync(0xffffffffu, mx0, off));
            mx1 = fmaxf(mx1, __shfl_xor_sync(0xffffffffu, mx1, off));
        }
        float nm0 = fmaxf(m0, mx0), nm1 = fmaxf(m1, mx1);
        float sum0 = 0.f, sum1 = 0.f;
        #pragma unroll
        for (int nt = 0; nt < 8; nt++) {
            sacc[nt][0] = __expf(sacc[nt][0] - nm0);
            sacc[nt][1] = __expf(sacc[nt][1] - nm0);
            sacc[nt][2] = __expf(sacc[nt][2] - nm1);
            sacc[nt][3] = __expf(sacc[nt][3] - nm1);
            sum0 += sacc[nt][0] + sacc[nt][1];
            sum1 += sacc[nt][2] + sacc[nt][3];
        }
        #pragma unroll
        for (int off = 1; off <= 2; off <<= 1) {
            sum0 += __shfl_xor_sync(0xffffffffu, sum0, off);
            sum1 += __shfl_xor_sync(0xffffffffu, sum1, off);
        }
        float al0 = __expf(m0 - nm0), al1 = __expf(m1 - nm1);
        l0 = l0 * al0 + sum0; l1 = l1 * al1 + sum1;
        m0 = nm0; m1 = nm1;
        #pragma unroll
        for (int nt = 0; nt < 16; nt++) {
            oacc[nt][0] *= al0; oacc[nt][1] *= al0;
            oacc[nt][2] *= al1; oacc[nt][3] *= al1;
        }

        // ---- O += P Vt^T (P repacked in registers, hi/lo split) ----
        #pragma unroll
        for (int ks2 = 0; ks2 < 4; ks2++) {
            float* e = sacc[2 * ks2];
            float* o = sacc[2 * ks2 + 1];
            float eh[4], oh[4];
            #pragma unroll
            for (int j = 0; j < 4; j++) { eh[j] = bf_hi(e[j]); oh[j] = bf_hi(o[j]); }
            uint32_t pa_h[4], pa_l[4];
            pa_h[0] = pack_bf16f(eh[0], eh[1]);
            pa_h[1] = pack_bf16f(eh[2], eh[3]);
            pa_h[2] = pack_bf16f(oh[0], oh[1]);
            pa_h[3] = pack_bf16f(oh[2], oh[3]);
            pa_l[0] = pack_bf16f(e[0] - eh[0], e[1] - eh[1]);
            pa_l[1] = pack_bf16f(e[2] - eh[2], e[3] - eh[3]);
            pa_l[2] = pack_bf16f(o[0] - oh[0], o[1] - oh[1]);
            pa_l[3] = pack_bf16f(o[2] - oh[2], o[3] - oh[3]);
            #pragma unroll
            for (int g = 0; g < 8; g++) {
                uint32_t vh[4], vl[4];
                uint32_t addr = stv + (g * 16 + b_row) * VR + (ks2 * 16 + b_kh) * 2;
                ldsm4(vh, addr);
                ldsm4(vl, addr + SVH);
                #pragma unroll
                for (int h8 = 0; h8 < 2; h8++) {
                    const int nt = g * 2 + h8;
                    mma_bf16(oacc[nt], pa_h, vh[h8*2], vh[h8*2+1]);
                    mma_bf16(oacc[nt], pa_h, vl[h8*2], vl[h8*2+1]);
                    mma_bf16(oacc[nt], pa_l, vh[h8*2], vh[h8*2+1]);
                }
            }
        }
        __syncthreads();
    }

    // ---- epilogue: O/l -> bf16 hi/lo A-buffers for the Wo GEMM ----
    const float il0 = 1.f / l0, il1 = 1.f / l1;
    #pragma unroll
    for (int nt = 0; nt < 16; nt++) {
        int d = nt * 8 + (lane & 3) * 2;
        size_t i0 = ((size_t)b * SS + row0) * H_DIM + h * HD + d;
        size_t i1 = ((size_t)b * SS + row1) * H_DIM + h * HD + d;
        float v0 = oacc[nt][0] * il0, v1 = oacc[nt][1] * il0;
        float v2 = oacc[nt][2] * il1, v3 = oacc[nt][3] * il1;
        float h0 = bf_hi(v0), h1v = bf_hi(v1), h2 = bf_hi(v2), h3 = bf_hi(v3);
        *(uint32_t*)&Oh_g[i0] = pack_bf16f(h0, h1v);
        *(uint32_t*)&Ol_g[i0] = pack_bf16f(v0 - h0, v1 - h1v);
        *(uint32_t*)&Oh_g[i1] = pack_bf16f(h2, h3);
        *(uint32_t*)&Ol_g[i1] = pack_bf16f(v2 - h2, v3 - h3);
    }
}

// ---------------- launcher ----------------
extern "C" void kernel_launch(void* const* d_in, const int* in_sizes, int n_in,
                              void* d_out, int out_size)
{
    const float* hidden = (const float*)d_in[0];
    const float* Wqkv = (const float*)d_in[2];
    const float* bqkv = (const float*)d_in[3];
    const float* Wo   = (const float*)d_in[4];
    float* out = (float*)d_out;

    float *qkv;
    float2 *ropetab;
    __nv_bfloat16 *wqh, *wql, *woh, *wol, *ah, *al;
    __nv_bfloat16 *q_h, *q_l, *k_h, *k_l, *vt_h, *vt_l;
    cudaGetSymbolAddress((void**)&qkv, g_qkv);
    cudaGetSymbolAddress((void**)&ropetab, g_rope);
    cudaGetSymbolAddress((void**)&wqh, g_Wq_h);
    cudaGetSymbolAddress((void**)&wql, g_Wq_l);
    cudaGetSymbolAddress((void**)&woh, g_Wo_h);
    cudaGetSymbolAddress((void**)&wol, g_Wo_l);
    cudaGetSymbolAddress((void**)&ah, g_A_h);
    cudaGetSymbolAddress((void**)&al, g_A_l);
    cudaGetSymbolAddress((void**)&q_h, g_Qh);
    cudaGetSymbolAddress((void**)&q_l, g_Ql);
    cudaGetSymbolAddress((void**)&k_h, g_Kh);
    cudaGetSymbolAddress((void**)&k_l, g_Kl);
    cudaGetSymbolAddress((void**)&vt_h, g_Vth);
    cudaGetSymbolAddress((void**)&vt_l, g_Vtl);

    // weight transpose+split + rope table + hidden split
    {
        dim3 g1(QKV_DIM / 32, H_DIM / 32);
        transpose_split_kernel<<<g1, 256>>>(Wqkv, wqh, wql, H_DIM, QKV_DIM);
        dim3 g2(H_DIM / 32, H_DIM / 32);
        transpose_split_kernel<<<g2, 256>>>(Wo, woh, wol, H_DIM, H_DIM);
        int nt = SS * (ROT/2);
        rope_table_kernel<<<(nt + 255) / 256, 256>>>(ropetab);
        int n4 = TOK * H_DIM / 4;
        split_kernel<<<(n4 + 255) / 256, 256>>>((const float4*)hidden,
                                                (__nv_bfloat162*)ah, (__nv_bfloat162*)al, n4);
    }
    // QKV GEMM (HMMA) + bias
    {
        cudaFuncSetAttribute(gemm_tc_kernel,
                             cudaFuncAttributeMaxDynamicSharedMemorySize, GSMEM);
        dim3 grid(QKV_DIM / BNg, TOK / BMg);
        gemm_tc_kernel<<<grid, 256, GSMEM>>>(ah, al, wqh, wql, bqkv, qkv,
                                             TOK, QKV_DIM, H_DIM);
    }
    // rope + split into attention layouts
    {
        int total = TOK * NSLOT * (HD/2);
        rope_split_kernel<<<(total + 255) / 256, 256>>>(qkv, ropetab,
            q_h, q_l, k_h, k_l, vt_h, vt_l);
    }
    // HMMA flash attention (writes bf16 hi/lo directly into Wo's A buffers)
    {
        cudaFuncSetAttribute(attn_kernel,
                             cudaFuncAttributeMaxDynamicSharedMemorySize, ASMEM);
        dim3 grid(SS / AQ, NH, BB);
        attn_kernel<<<grid, 256, ASMEM>>>(q_h, q_l, k_h, k_l, vt_h, vt_l, ah, al);
    }
    // output GEMM (HMMA)
    {
        dim3 grid(H_DIM / BNg, TOK / BMg);
        gemm_tc_kernel<<<grid, 256, GSMEM>>>(ah, al, woh, wol, nullptr, out,
                                             TOK, H_DIM, H_DIM);
    }
}

// round 6
// speedup vs baseline: 4.1179x; 1.2962x over previous
#include <cuda_runtime.h>
#include <cuda_bf16.h>
#include <cuda_fp16.h>
#include <math.h>
#include <stdint.h>

// ---------------- problem constants ----------------
#define H_DIM 4096
#define NH 32
#define NKV 2
#define HD 128
#define ROT 64
#define BB 2
#define SS 2048
#define QKV_DIM ((NH + 2*NKV)*HD)   // 4608
#define TOK (BB*SS)                 // 4096
#define NSLOT (NH + 2*NKV)          // 36

// scratch (allocation-free rule: device globals)
__device__ __half g_W1[(size_t)QKV_DIM * H_DIM];     // Wqkv^T fp16 [N][K]
__device__ __half g_W2[(size_t)H_DIM * H_DIM];       // Wo^T fp16 [N][K]
__device__ __half g_A_h[(size_t)TOK * H_DIM];
__device__ __half g_A_l[(size_t)TOK * H_DIM];
__device__ __nv_bfloat16 g_Qh[(size_t)TOK * NH * HD];
__device__ __nv_bfloat16 g_Ql[(size_t)TOK * NH * HD];
__device__ __nv_bfloat16 g_Kh[(size_t)TOK * NKV * HD];
__device__ __nv_bfloat16 g_Kl[(size_t)TOK * NKV * HD];
__device__ __nv_bfloat16 g_Vth[(size_t)TOK * NKV * HD];
__device__ __nv_bfloat16 g_Vtl[(size_t)TOK * NKV * HD];
__device__ float2 g_rope[SS * (ROT/2)];

// ---------------- PTX helpers (arch-generic: HMMA / ldmatrix / cp.async) ----
__device__ __forceinline__ uint32_t smem_u32(const void* p) {
    uint32_t a;
    asm("{ .reg .u64 t; cvta.to.shared.u64 t, %1; cvt.u32.u64 %0, t; }"
        : "=r"(a) : "l"(p));
    return a;
}
__device__ __forceinline__ void ldsm4(uint32_t* r, uint32_t addr) {
    asm volatile("ldmatrix.sync.aligned.m8n8.x4.shared.b16 {%0,%1,%2,%3}, [%4];"
                 : "=r"(r[0]), "=r"(r[1]), "=r"(r[2]), "=r"(r[3]) : "r"(addr));
}
__device__ __forceinline__ void mma_bf16(float* d, const uint32_t* a,
                                         uint32_t b0, uint32_t b1) {
    asm volatile("mma.sync.aligned.m16n8k16.row.col.f32.bf16.bf16.f32 "
                 "{%0,%1,%2,%3}, {%4,%5,%6,%7}, {%8,%9}, {%0,%1,%2,%3};"
                 : "+f"(d[0]), "+f"(d[1]), "+f"(d[2]), "+f"(d[3])
                 : "r"(a[0]), "r"(a[1]), "r"(a[2]), "r"(a[3]), "r"(b0), "r"(b1));
}
__device__ __forceinline__ void mma_f16(float* d, const uint32_t* a,
                                        uint32_t b0, uint32_t b1) {
    asm volatile("mma.sync.aligned.m16n8k16.row.col.f32.f16.f16.f32 "
                 "{%0,%1,%2,%3}, {%4,%5,%6,%7}, {%8,%9}, {%0,%1,%2,%3};"
                 : "+f"(d[0]), "+f"(d[1]), "+f"(d[2]), "+f"(d[3])
                 : "r"(a[0]), "r"(a[1]), "r"(a[2]), "r"(a[3]), "r"(b0), "r"(b1));
}
__device__ __forceinline__ uint32_t pack_bf16f(float lo, float hi) {
    uint32_t r;
    asm("cvt.rn.bf16x2.f32 %0, %1, %2;" : "=r"(r) : "f"(hi), "f"(lo));
    return r;
}
__device__ __forceinline__ float bf_hi(float x) {
    return __bfloat162float(__float2bfloat16(x));
}
__device__ __forceinline__ float h_hi(float x) {
    return __half2float(__float2half_rn(x));
}
#define CP_ASYNC16(dst, src) \
    asm volatile("cp.async.cg.shared.global [%0], [%1], 16;" :: "r"(dst), "l"(src))
#define CP_COMMIT() asm volatile("cp.async.commit_group;" ::: "memory")
#define CP_WAIT1() asm volatile("cp.async.wait_group 1;" ::: "memory")
#define CP_WAIT0() asm volatile("cp.async.wait_group 0;" ::: "memory")

// ---------------- conversion kernels ----------------
// fp32 -> fp16 hi/lo split
__global__ void split_f16_kernel(const float4* __restrict__ x,
                                 __half2* __restrict__ h,
                                 __half2* __restrict__ l, int n4)
{
    int i = blockIdx.x * blockDim.x + threadIdx.x;
    if (i >= n4) return;
    float4 v = x[i];
    float h0 = h_hi(v.x), h1 = h_hi(v.y), h2 = h_hi(v.z), h3 = h_hi(v.w);
    h[2*i]   = __floats2half2_rn(h0, h1);
    h[2*i+1] = __floats2half2_rn(h2, h3);
    l[2*i]   = __floats2half2_rn(v.x - h0, v.y - h1);
    l[2*i+1] = __floats2half2_rn(v.z - h2, v.w - h3);
}

// W [K][N] row-major -> T [N][K] fp16 (single rounding)
__global__ void transpose_f16_kernel(const float* __restrict__ W,
                                     __half* __restrict__ T, int K, int N)
{
    __shared__ float t[32][33];
    int n0 = blockIdx.x * 32, k0 = blockIdx.y * 32;
    int tx = threadIdx.x & 31, g = threadIdx.x >> 5;
    #pragma unroll
    for (int j = 0; j < 4; j++) {
        int ky = g * 4 + j;
        t[ky][tx] = W[(size_t)(k0 + ky) * N + n0 + tx];
    }
    __syncthreads();
    #pragma unroll
    for (int j = 0; j < 4; j++) {
        int ny = g * 4 + j;
        T[(size_t)(n0 + ny) * K + k0 + tx] = __float2half_rn(t[tx][ny]);
    }
}

// rope cos/sin table (accurate double trig, matches jax fp32 rounding)
__global__ void rope_table_kernel(float2* __restrict__ tab)
{
    int idx = blockIdx.x * blockDim.x + threadIdx.x;
    if (idx >= SS * (ROT/2)) return;
    int s = idx >> 5, i = idx & 31;
    float inv  = 1.0f / powf(10000.0f, (float)(2 * i) / (float)ROT);
    float freq = (float)s * inv;
    double fd = (double)freq;
    tab[idx] = make_float2((float)cos(fd), (float)sin(fd));
}

// ---------------- fp16 2-term HMMA GEMM: C = A @ W^T (+bias) -----------------
// MODE 0: plain fp32 output to C.
// MODE 1: QKV epilogue — bias + RoPE + bf16 hi/lo split scatter to Q/K/Vt.
#define BMg 128
#define BNg 128
#define BKg 32
#define ROWB 80
#define TSZ (128*ROWB)     // 10240
#define STGSZ (3*TSZ)      // 30720 (Ah, Al, W)
#define GSMEM (2*STGSZ)    // 61440

template<int MODE>
__global__ __launch_bounds__(256, 2) void gemm_f16_kernel(
    const __half* __restrict__ Ah, const __half* __restrict__ Al,
    const __half* __restrict__ Bw,
    const float* __restrict__ bias, float* __restrict__ C,
    int M, int N, int K,
    const float2* __restrict__ tab,
    __nv_bfloat16* __restrict__ Qh, __nv_bfloat16* __restrict__ Ql,
    __nv_bfloat16* __restrict__ Kh2, __nv_bfloat16* __restrict__ Kl2,
    __nv_bfloat16* __restrict__ Vth, __nv_bfloat16* __restrict__ Vtl)
{
    extern __shared__ char smem[];
    const uint32_t sb = smem_u32(smem);
    const int tid = threadIdx.x;
    const int wid = tid >> 5;
    const int lane = tid & 31;
    const int m0 = blockIdx.y * BMg;
    const int n0 = blockIdx.x * BNg;
    const int NC = K / BKg;

    const int wm = (wid >> 2) * 64;
    const int wn = (wid & 3) * 32;

    const int a_row = (lane & 7) + ((lane >> 3) & 1) * 8;
    const int a_kh  = (lane >> 4) * 8;
    const int b_row = (lane & 7) + ((lane >> 4) & 1) * 8;
    const int b_kh  = ((lane >> 3) & 1) * 8;

    float acc[4][4][4];
    #pragma unroll
    for (int i = 0; i < 4; i++)
        #pragma unroll
        for (int j = 0; j < 4; j++)
            #pragma unroll
            for (int q = 0; q < 4; q++) acc[i][j][q] = 0.f;

    const int lr_lo = tid >> 2;
    const int lc    = tid & 3;
    auto issue_loads = [&](int c, int buf) {
        const int k0 = c * BKg;
        const uint32_t sbuf = sb + buf * STGSZ;
        #pragma unroll
        for (int i = 0; i < 6; i++) {
            const int tensor = i >> 1;
            const int r = ((i & 1) << 6) + lr_lo;
            const __half* src;
            if (tensor == 0)      src = Ah + (size_t)(m0 + r) * K + k0 + lc * 8;
            else if (tensor == 1) src = Al + (size_t)(m0 + r) * K + k0 + lc * 8;
            else                  src = Bw + (size_t)(n0 + r) * K + k0 + lc * 8;
            uint32_t dst = sbuf + tensor * TSZ + r * ROWB + lc * 16;
            CP_ASYNC16(dst, src);
        }
        CP_COMMIT();
    };

    auto compute = [&](int buf) {
        const uint32_t sbuf = sb + buf * STGSZ;
        #pragma unroll
        for (int ks = 0; ks < 2; ks++) {
            uint32_t br[2][4];
            #pragma unroll
            for (int g = 0; g < 2; g++) {
                uint32_t addr = sbuf + 2 * TSZ +
                    (wn + g * 16 + b_row) * ROWB + (ks * 16 + b_kh) * 2;
                ldsm4(br[g], addr);
            }
            #pragma unroll
            for (int mt = 0; mt < 4; mt++) {
                uint32_t ah[4], al[4];
                uint32_t addrA = sbuf +
                    (wm + mt * 16 + a_row) * ROWB + (ks * 16 + a_kh) * 2;
                ldsm4(ah, addrA);
                ldsm4(al, addrA + TSZ);
                #pragma unroll
                for (int g = 0; g < 2; g++) {
                    #pragma unroll
                    for (int h8 = 0; h8 < 2; h8++) {
                        const int nt = g * 2 + h8;
                        mma_f16(acc[mt][nt], ah, br[g][h8*2], br[g][h8*2+1]);
                        mma_f16(acc[mt][nt], al, br[g][h8*2], br[g][h8*2+1]);
                    }
                }
            }
        }
    };

    issue_loads(0, 0);
    for (int c = 0; c < NC; ++c) {
        const int buf = c & 1;
        if (c + 1 < NC) {
            issue_loads(c + 1, buf ^ 1);
            CP_WAIT1();
        } else {
            CP_WAIT0();
        }
        __syncthreads();
        compute(buf);
        __syncthreads();
    }

    if (MODE == 0) {
        #pragma unroll
        for (int mt = 0; mt < 4; mt++) {
            const int m = m0 + wm + mt * 16 + (lane >> 2);
            #pragma unroll
            for (int nt = 0; nt < 4; nt++) {
                const int n = n0 + wn + nt * 8 + (lane & 3) * 2;
                float b0 = 0.f, b1 = 0.f;
                if (bias) { b0 = bias[n]; b1 = bias[n + 1]; }
                float2 v0, v1;
                v0.x = acc[mt][nt][0] + b0; v0.y = acc[mt][nt][1] + b1;
                v1.x = acc[mt][nt][2] + b0; v1.y = acc[mt][nt][3] + b1;
                *(float2*)&C[(size_t)m * N + n] = v0;
                *(float2*)&C[(size_t)(m + 8) * N + n] = v1;
            }
        }
    } else {
        // QKV epilogue: bias + RoPE + bf16 hi/lo split into Q / K / Vt layouts
        const int slot = n0 >> 7;                 // BNg == HD: one head slot per CTA col
        const int kvv = slot - NH;
        const int kvslot = slot - NH - NKV;
        #pragma unroll
        for (int mt = 0; mt < 4; mt++) {
            const int mrow = m0 + wm + mt * 16 + (lane >> 2);
            const int s0 = mrow & (SS - 1), bb0 = mrow >> 11;
            const int s1 = (mrow + 8) & (SS - 1), bb1 = (mrow + 8) >> 11;
            #pragma unroll
            for (int nt = 0; nt < 4; nt++) {
                const int n = n0 + wn + nt * 8 + (lane & 3) * 2;
                const int d = n & 127;
                float v0 = acc[mt][nt][0] + bias[n];
                float v1 = acc[mt][nt][1] + bias[n + 1];
                float v2 = acc[mt][nt][2] + bias[n];
                float v3 = acc[mt][nt][3] + bias[n + 1];
                if (slot < NH + NKV && d < ROT) {
                    float2 c0 = tab[s0 * (ROT/2) + (d >> 1)];
                    float o0 = v0 * c0.x - v1 * c0.y;
                    float o1 = v1 * c0.x + v0 * c0.y;
                    v0 = o0; v1 = o1;
                    float2 c1 = tab[s1 * (ROT/2) + (d >> 1)];
                    float o2 = v2 * c1.x - v3 * c1.y;
                    float o3 = v3 * c1.x + v2 * c1.y;
                    v2 = o2; v3 = o3;
                }
                float h0 = bf_hi(v0), h1 = bf_hi(v1);
                float h2 = bf_hi(v2), h3 = bf_hi(v3);
                if (slot < NH) {
                    size_t base0 = ((size_t)(bb0 * NH + slot) * SS + s0) * HD + d;
                    size_t base1 = ((size_t)(bb1 * NH + slot) * SS + s1) * HD + d;
                    *(uint32_t*)&Qh[base0] = pack_bf16f(h0, h1);
                    *(uint32_t*)&Ql[base0] = pack_bf16f(v0 - h0, v1 - h1);
                    *(uint32_t*)&Qh[base1] = pack_bf16f(h2, h3);
                    *(uint32_t*)&Ql[base1] = pack_bf16f(v2 - h2, v3 - h3);
                } else if (slot < NH + NKV) {
                    size_t base0 = ((size_t)(bb0 * NKV + kvv) * SS + s0) * HD + d;
                    size_t base1 = ((size_t)(bb1 * NKV + kvv) * SS + s1) * HD + d;
                    *(uint32_t*)&Kh2[base0] = pack_bf16f(h0, h1);
                    *(uint32_t*)&Kl2[base0] = pack_bf16f(v0 - h0, v1 - h1);
                    *(uint32_t*)&Kh2[base1] = pack_bf16f(h2, h3);
                    *(uint32_t*)&Kl2[base1] = pack_bf16f(v2 - h2, v3 - h3);
                } else {
                    size_t vb0 = ((size_t)(bb0 * NKV + kvslot) * HD + d) * SS + s0;
                    size_t vb1 = ((size_t)(bb1 * NKV + kvslot) * HD + d) * SS + s1;
                    Vth[vb0]      = __float2bfloat16(h0);
                    Vtl[vb0]      = __float2bfloat16(v0 - h0);
                    Vth[vb0 + SS] = __float2bfloat16(h1);
                    Vtl[vb0 + SS] = __float2bfloat16(v1 - h1);
                    Vth[vb1]      = __float2bfloat16(h2);
                    Vtl[vb1]      = __float2bfloat16(v2 - h2);
                    Vth[vb1 + SS] = __float2bfloat16(h3);
                    Vtl[vb1 + SS] = __float2bfloat16(v3 - h3);
                }
            }
        }
    }
}

// ---------------- HMMA flash attention (bf16 hi/lo split) --------------------
#define AQ 128
#define AK 64
#define QR 272
#define VR 144
#define SQH (AQ*QR)
#define SKH (AK*QR)
#define SVH (HD*VR)
#define STGA (2*SKH + 2*SVH)
#define ASMEM (2*SQH + 2*STGA)

__global__ __launch_bounds__(256, 1) void attn_kernel(
    const __nv_bfloat16* __restrict__ Qh_g, const __nv_bfloat16* __restrict__ Ql_g,
    const __nv_bfloat16* __restrict__ Kh_g, const __nv_bfloat16* __restrict__ Kl_g,
    const __nv_bfloat16* __restrict__ Vth_g, const __nv_bfloat16* __restrict__ Vtl_g,
    __half* __restrict__ Oh_g, __half* __restrict__ Ol_g)
{
    extern __shared__ char smem[];
    const uint32_t sb = smem_u32(smem);
    const int tid = threadIdx.x;
    const int wid = tid >> 5;
    const int lane = tid & 31;
    const int qt = blockIdx.x;
    const int h  = blockIdx.y;
    const int b  = blockIdx.z;
    const int kvh = h / (NH / NKV);
    const int qbase = qt * AQ;
    const int ktmax = 2 * qt + 1;

    const size_t qoff = ((size_t)(b * NH + h) * SS + qbase) * HD;
    const size_t koff = ((size_t)(b * NKV + kvh) * SS) * HD;
    const size_t voff = ((size_t)(b * NKV + kvh) * HD) * SS;

    const int a_row = (lane & 7) + ((lane >> 3) & 1) * 8;
    const int a_kh  = (lane >> 4) * 8;
    const int b_row = (lane & 7) + ((lane >> 4) & 1) * 8;
    const int b_kh  = ((lane >> 3) & 1) * 8;

    #pragma unroll
    for (int i = 0; i < 8; i++) {
        int flat = i * 256 + tid;
        int r = flat >> 4, u = flat & 15;
        *(uint4*)(smem + r * QR + u * 16) =
            *(const uint4*)(Qh_g + qoff + (size_t)r * HD + u * 8);
        *(uint4*)(smem + SQH + r * QR + u * 16) =
            *(const uint4*)(Ql_g + qoff + (size_t)r * HD + u * 8);
    }

    auto issue_kv = [&](int kt, int buf) {
        const int kbase = kt * AK;
        const uint32_t st = sb + 2 * SQH + buf * STGA;
        #pragma unroll
        for (int i = 0; i < 8; i++) {
            int flat = i * 256 + tid;
            int tensor = flat >> 10, rem = flat & 1023;
            int r = rem >> 4, u = rem & 15;
            const __nv_bfloat16* src = (tensor ? Kl_g : Kh_g) +
                koff + (size_t)(kbase + r) * HD + u * 8;
            CP_ASYNC16(st + tensor * SKH + r * QR + u * 16, src);
        }
        #pragma unroll
        for (int i = 0; i < 8; i++) {
            int flat = i * 256 + tid;
            int tensor = flat >> 10, rem = flat & 1023;
            int r = rem >> 3, u = rem & 7;
            const __nv_bfloat16* src = (tensor ? Vtl_g : Vth_g) +
                voff + (size_t)r * SS + kbase + u * 8;
            CP_ASYNC16(st + 2 * SKH + tensor * SVH + r * VR + u * 16, src);
        }
        CP_COMMIT();
    };

    float oacc[16][4];
    #pragma unroll
    for (int i = 0; i < 16; i++)
        #pragma unroll
        for (int j = 0; j < 4; j++) oacc[i][j] = 0.f;
    float m0 = -INFINITY, m1 = -INFINITY, l0 = 0.f, l1 = 0.f;
    const float scale = 0.08838834764831845f;
    const int row0 = qbase + wid * 16 + (lane >> 2);
    const int row1 = row0 + 8;

    issue_kv(0, 0);

    for (int kt = 0; kt <= ktmax; ++kt) {
        const int buf = kt & 1;
        const int kbase = kt * AK;
        if (kt + 1 <= ktmax) { issue_kv(kt + 1, buf ^ 1); CP_WAIT1(); }
        else CP_WAIT0();
        __syncthreads();

        const uint32_t stk = sb + 2 * SQH + buf * STGA;
        const uint32_t stv = stk + 2 * SKH;

        float sacc[8][4];
        #pragma unroll
        for (int i = 0; i < 8; i++)
            #pragma unroll
            for (int j = 0; j < 4; j++) sacc[i][j] = 0.f;
        #pragma unroll
        for (int ks = 0; ks < 8; ks++) {
            uint32_t bh[4][4], bl[4][4];
            #pragma unroll
            for (int g = 0; g < 4; g++) {
                uint32_t addr = stk + (g * 16 + b_row) * QR + (ks * 16 + b_kh) * 2;
                ldsm4(bh[g], addr);
                ldsm4(bl[g], addr + SKH);
            }
            uint32_t qa_h[4], qa_l[4];
            uint32_t addrA = sb + (wid * 16 + a_row) * QR + (ks * 16 + a_kh) * 2;
            ldsm4(qa_h, addrA);
            ldsm4(qa_l, addrA + SQH);
            #pragma unroll
            for (int g = 0; g < 4; g++) {
                #pragma unroll
                for (int h8 = 0; h8 < 2; h8++) {
                    const int nt = g * 2 + h8;
                    mma_bf16(sacc[nt], qa_h, bh[g][h8*2], bh[g][h8*2+1]);
                    mma_bf16(sacc[nt], qa_h, bl[g][h8*2], bl[g][h8*2+1]);
                    mma_bf16(sacc[nt], qa_l, bh[g][h8*2], bh[g][h8*2+1]);
                }
            }
        }

        const bool need_mask = (kbase + AK - 1) > (qbase + wid * 16);
        #pragma unroll
        for (int nt = 0; nt < 8; nt++) {
            int c0 = kbase + nt * 8 + (lane & 3) * 2;
            #pragma unroll
            for (int j = 0; j < 4; j++) sacc[nt][j] *= scale;
            if (need_mask) {
                if (c0     > row0) sacc[nt][0] = -INFINITY;
                if (c0 + 1 > row0) sacc[nt][1] = -INFINITY;
                if (c0     > row1) sacc[nt][2] = -INFINITY;
                if (c0 + 1 > row1) sacc[nt][3] = -INFINITY;
            }
        }

        float mx0 = -INFINITY, mx1 = -INFINITY;
        #pragma unroll
        for (int nt = 0; nt < 8; nt++) {
            mx0 = fmaxf(mx0, fmaxf(sacc[nt][0], sacc[nt][1]));
            mx1 = fmaxf(mx1, fmaxf(sacc[nt][2], sacc[nt][3]));
        }
        #pragma unroll
        for (int off = 1; off <= 2; off <<= 1) {
            mx0 = fmaxf(mx0, __shfl_xor_sync(0xffffffffu, mx0, off));
            mx1 = fmaxf(mx1, __shfl_xor_sync(0xffffffffu, mx1, off));
        }
        float nm0 = fmaxf(m0, mx0), nm1 = fmaxf(m1, mx1);
        float sum0 = 0.f, sum1 = 0.f;
        #pragma unroll
        for (int nt = 0; nt < 8; nt++) {
            sacc[nt][0] = __expf(sacc[nt][0] - nm0);
            sacc[nt][1] = __expf(sacc[nt][1] - nm0);
            sacc[nt][2] = __expf(sacc[nt][2] - nm1);
            sacc[nt][3] = __expf(sacc[nt][3] - nm1);
            sum0 += sacc[nt][0] + sacc[nt][1];
            sum1 += sacc[nt][2] + sacc[nt][3];
        }
        #pragma unroll
        for (int off = 1; off <= 2; off <<= 1) {
            sum0 += __shfl_xor_sync(0xffffffffu, sum0, off);
            sum1 += __shfl_xor_sync(0xffffffffu, sum1, off);
        }
        float al0 = __expf(m0 - nm0), al1 = __expf(m1 - nm1);
        l0 = l0 * al0 + sum0; l1 = l1 * al1 + sum1;
        m0 = nm0; m1 = nm1;
        #pragma unroll
        for (int nt = 0; nt < 16; nt++) {
            oacc[nt][0] *= al0; oacc[nt][1] *= al0;
            oacc[nt][2] *= al1; oacc[nt][3] *= al1;
        }

        #pragma unroll
        for (int ks2 = 0; ks2 < 4; ks2++) {
            float* e = sacc[2 * ks2];
            float* o = sacc[2 * ks2 + 1];
            float eh[4], oh[4];
            #pragma unroll
            for (int j = 0; j < 4; j++) { eh[j] = bf_hi(e[j]); oh[j] = bf_hi(o[j]); }
            uint32_t pa_h[4], pa_l[4];
            pa_h[0] = pack_bf16f(eh[0], eh[1]);
            pa_h[1] = pack_bf16f(eh[2], eh[3]);
            pa_h[2] = pack_bf16f(oh[0], oh[1]);
            pa_h[3] = pack_bf16f(oh[2], oh[3]);
            pa_l[0] = pack_bf16f(e[0] - eh[0], e[1] - eh[1]);
            pa_l[1] = pack_bf16f(e[2] - eh[2], e[3] - eh[3]);
            pa_l[2] = pack_bf16f(o[0] - oh[0], o[1] - oh[1]);
            pa_l[3] = pack_bf16f(o[2] - oh[2], o[3] - oh[3]);
            #pragma unroll
            for (int g = 0; g < 8; g++) {
                uint32_t vh[4], vl[4];
                uint32_t addr = stv + (g * 16 + b_row) * VR + (ks2 * 16 + b_kh) * 2;
                ldsm4(vh, addr);
                ldsm4(vl, addr + SVH);
                #pragma unroll
                for (int h8 = 0; h8 < 2; h8++) {
                    const int nt = g * 2 + h8;
                    mma_bf16(oacc[nt], pa_h, vh[h8*2], vh[h8*2+1]);
                    mma_bf16(oacc[nt], pa_h, vl[h8*2], vl[h8*2+1]);
                    mma_bf16(oacc[nt], pa_l, vh[h8*2], vh[h8*2+1]);
                }
            }
        }
        __syncthreads();
    }

    // ---- epilogue: O/l -> fp16 hi/lo A-buffers for the Wo GEMM ----
    const float il0 = 1.f / l0, il1 = 1.f / l1;
    #pragma unroll
    for (int nt = 0; nt < 16; nt++) {
        int d = nt * 8 + (lane & 3) * 2;
        size_t i0 = ((size_t)b * SS + row0) * H_DIM + h * HD + d;
        size_t i1 = ((size_t)b * SS + row1) * H_DIM + h * HD + d;
        float v0 = oacc[nt][0] * il0, v1 = oacc[nt][1] * il0;
        float v2 = oacc[nt][2] * il1, v3 = oacc[nt][3] * il1;
        float h0 = h_hi(v0), h1v = h_hi(v1), h2 = h_hi(v2), h3 = h_hi(v3);
        *(__half2*)&Oh_g[i0] = __floats2half2_rn(h0, h1v);
        *(__half2*)&Ol_g[i0] = __floats2half2_rn(v0 - h0, v1 - h1v);
        *(__half2*)&Oh_g[i1] = __floats2half2_rn(h2, h3);
        *(__half2*)&Ol_g[i1] = __floats2half2_rn(v2 - h2, v3 - h3);
    }
}

// ---------------- launcher ----------------
extern "C" void kernel_launch(void* const* d_in, const int* in_sizes, int n_in,
                              void* d_out, int out_size)
{
    const float* hidden = (const float*)d_in[0];
    const float* Wqkv = (const float*)d_in[2];
    const float* bqkv = (const float*)d_in[3];
    const float* Wo   = (const float*)d_in[4];
    float* out = (float*)d_out;

    float2 *ropetab;
    __half *w1, *w2, *ah, *al;
    __nv_bfloat16 *q_h, *q_l, *k_h, *k_l, *vt_h, *vt_l;
    cudaGetSymbolAddress((void**)&ropetab, g_rope);
    cudaGetSymbolAddress((void**)&w1, g_W1);
    cudaGetSymbolAddress((void**)&w2, g_W2);
    cudaGetSymbolAddress((void**)&ah, g_A_h);
    cudaGetSymbolAddress((void**)&al, g_A_l);
    cudaGetSymbolAddress((void**)&q_h, g_Qh);
    cudaGetSymbolAddress((void**)&q_l, g_Ql);
    cudaGetSymbolAddress((void**)&k_h, g_Kh);
    cudaGetSymbolAddress((void**)&k_l, g_Kl);
    cudaGetSymbolAddress((void**)&vt_h, g_Vth);
    cudaGetSymbolAddress((void**)&vt_l, g_Vtl);

    // prep: weight transpose fp16, rope table, hidden fp16 hi/lo split
    {
        dim3 g1(QKV_DIM / 32, H_DIM / 32);
        transpose_f16_kernel<<<g1, 256>>>(Wqkv, w1, H_DIM, QKV_DIM);
        dim3 g2(H_DIM / 32, H_DIM / 32);
        transpose_f16_kernel<<<g2, 256>>>(Wo, w2, H_DIM, H_DIM);
        int nt = SS * (ROT/2);
        rope_table_kernel<<<(nt + 255) / 256, 256>>>(ropetab);
        int n4 = TOK * H_DIM / 4;
        split_f16_kernel<<<(n4 + 255) / 256, 256>>>((const float4*)hidden,
                                                    (__half2*)ah, (__half2*)al, n4);
    }
    // QKV GEMM fused with bias + RoPE + split scatter
    {
        cudaFuncSetAttribute(gemm_f16_kernel<1>,
                             cudaFuncAttributeMaxDynamicSharedMemorySize, GSMEM);
        dim3 grid(QKV_DIM / BNg, TOK / BMg);
        gemm_f16_kernel<1><<<grid, 256, GSMEM>>>(ah, al, w1, bqkv, nullptr,
                                                 TOK, QKV_DIM, H_DIM, ropetab,
                                                 q_h, q_l, k_h, k_l, vt_h, vt_l);
    }
    // HMMA flash attention (writes fp16 hi/lo directly into Wo's A buffers)
    {
        cudaFuncSetAttribute(attn_kernel,
                             cudaFuncAttributeMaxDynamicSharedMemorySize, ASMEM);
        dim3 grid(SS / AQ, NH, BB);
        attn_kernel<<<grid, 256, ASMEM>>>(q_h, q_l, k_h, k_l, vt_h, vt_l, ah, al);
    }
    // output GEMM
    {
        cudaFuncSetAttribute(gemm_f16_kernel<0>,
                             cudaFuncAttributeMaxDynamicSharedMemorySize, GSMEM);
        dim3 grid(H_DIM / BNg, TOK / BMg);
        gemm_f16_kernel<0><<<grid, 256, GSMEM>>>(ah, al, w2, nullptr, out,
                                                 TOK, H_DIM, H_DIM, nullptr,
                                                 nullptr, nullptr, nullptr, nullptr,
                                                 nullptr, nullptr);
    }
}

// round 8
// speedup vs baseline: 4.4057x; 1.0699x over previous
#include <cuda_runtime.h>
#include <cuda_bf16.h>
#include <cuda_fp16.h>
#include <math.h>
#include <stdint.h>

// ---------------- problem constants ----------------
#define H_DIM 4096
#define NH 32
#define NKV 2
#define HD 128
#define ROT 64
#define BB 2
#define SS 2048
#define QKV_DIM ((NH + 2*NKV)*HD)   // 4608
#define TOK (BB*SS)                 // 4096

// scratch (allocation-free rule: device globals)
__device__ __half g_W1[(size_t)QKV_DIM * H_DIM];     // Wqkv^T fp16 [N][K]
__device__ __half g_W2[(size_t)H_DIM * H_DIM];       // Wo^T fp16 [N][K]
__device__ __half g_A_h[(size_t)TOK * H_DIM];
__device__ __half g_A_l[(size_t)TOK * H_DIM];
__device__ __half g_Qh[(size_t)TOK * NH * HD];
__device__ __half g_Ql[(size_t)TOK * NH * HD];
__device__ __half g_K1[(size_t)TOK * NKV * HD];
__device__ __half g_Vt[(size_t)TOK * NKV * HD];
__device__ float2 g_rope[SS * (ROT/2)];

// ---------------- PTX helpers ----------------
__device__ __forceinline__ uint32_t smem_u32(const void* p) {
    uint32_t a;
    asm("{ .reg .u64 t; cvta.to.shared.u64 t, %1; cvt.u32.u64 %0, t; }"
        : "=r"(a) : "l"(p));
    return a;
}
__device__ __forceinline__ void ldsm4(uint32_t* r, uint32_t addr) {
    asm volatile("ldmatrix.sync.aligned.m8n8.x4.shared.b16 {%0,%1,%2,%3}, [%4];"
                 : "=r"(r[0]), "=r"(r[1]), "=r"(r[2]), "=r"(r[3]) : "r"(addr));
}
__device__ __forceinline__ void mma_f16(float* d, const uint32_t* a,
                                        uint32_t b0, uint32_t b1) {
    asm volatile("mma.sync.aligned.m16n8k16.row.col.f32.f16.f16.f32 "
                 "{%0,%1,%2,%3}, {%4,%5,%6,%7}, {%8,%9}, {%0,%1,%2,%3};"
                 : "+f"(d[0]), "+f"(d[1]), "+f"(d[2]), "+f"(d[3])
                 : "r"(a[0]), "r"(a[1]), "r"(a[2]), "r"(a[3]), "r"(b0), "r"(b1));
}
__device__ __forceinline__ uint32_t pack_h2(float lo, float hi) {
    __half2 t = __floats2half2_rn(lo, hi);
    return *(uint32_t*)&t;
}
__device__ __forceinline__ float h_hi(float x) {
    return __half2float(__float2half_rn(x));
}
#define CP_ASYNC16(dst, src) \
    asm volatile("cp.async.cg.shared.global [%0], [%1], 16;" :: "r"(dst), "l"(src))
#define CP_COMMIT() asm volatile("cp.async.commit_group;" ::: "memory")
#define CP_WAIT2() asm volatile("cp.async.wait_group 2;" ::: "memory")
#define CP_WAIT1() asm volatile("cp.async.wait_group 1;" ::: "memory")
#define CP_WAIT0() asm volatile("cp.async.wait_group 0;" ::: "memory")

// ---------------- conversion kernels ----------------
__global__ void split_f16_kernel(const float4* __restrict__ x,
                                 __half2* __restrict__ h,
                                 __half2* __restrict__ l, int n4)
{
    int i = blockIdx.x * blockDim.x + threadIdx.x;
    if (i >= n4) return;
    float4 v = x[i];
    float h0 = h_hi(v.x), h1 = h_hi(v.y), h2 = h_hi(v.z), h3 = h_hi(v.w);
    h[2*i]   = __floats2half2_rn(h0, h1);
    h[2*i+1] = __floats2half2_rn(h2, h3);
    l[2*i]   = __floats2half2_rn(v.x - h0, v.y - h1);
    l[2*i+1] = __floats2half2_rn(v.z - h2, v.w - h3);
}

__global__ void transpose_f16_kernel(const float* __restrict__ W,
                                     __half* __restrict__ T, int K, int N)
{
    __shared__ float t[32][33];
    int n0 = blockIdx.x * 32, k0 = blockIdx.y * 32;
    int tx = threadIdx.x & 31, g = threadIdx.x >> 5;
    #pragma unroll
    for (int j = 0; j < 4; j++) {
        int ky = g * 4 + j;
        t[ky][tx] = W[(size_t)(k0 + ky) * N + n0 + tx];
    }
    __syncthreads();
    #pragma unroll
    for (int j = 0; j < 4; j++) {
        int ny = g * 4 + j;
        T[(size_t)(n0 + ny) * K + k0 + tx] = __float2half_rn(t[tx][ny]);
    }
}

__global__ void rope_table_kernel(float2* __restrict__ tab)
{
    int idx = blockIdx.x * blockDim.x + threadIdx.x;
    if (idx >= SS * (ROT/2)) return;
    int s = idx >> 5, i = idx & 31;
    float inv  = 1.0f / powf(10000.0f, (float)(2 * i) / (float)ROT);
    float freq = (float)s * inv;
    double fd = (double)freq;
    tab[idx] = make_float2((float)cos(fd), (float)sin(fd));
}

// ---------------- fp16 2-term HMMA GEMM (3-stage pipeline) -------------------
// MODE 0: plain fp32 output. MODE 1: QKV epilogue (bias+RoPE+scatter fp16).
#define BMg 128
#define BNg 128
#define BKg 32
#define ROWB 80
#define TSZ (128*ROWB)     // 10240
#define STGSZ (3*TSZ)      // 30720 (Ah, Al, W)
#define GSMEM (3*STGSZ)    // 92160 (3 stages)

template<int MODE>
__global__ __launch_bounds__(256, 2) void gemm_f16_kernel(
    const __half* __restrict__ Ah, const __half* __restrict__ Al,
    const __half* __restrict__ Bw,
    const float* __restrict__ bias, float* __restrict__ C,
    int M, int N, int K,
    const float2* __restrict__ tab,
    __half* __restrict__ Qh, __half* __restrict__ Ql,
    __half* __restrict__ Kq, __half* __restrict__ Vt)
{
    extern __shared__ char smem[];
    const uint32_t sb = smem_u32(smem);
    const int tid = threadIdx.x;
    const int wid = tid >> 5;
    const int lane = tid & 31;
    const int m0 = blockIdx.y * BMg;
    const int n0 = blockIdx.x * BNg;
    const int NC = K / BKg;

    const int wm = (wid >> 2) * 64;
    const int wn = (wid & 3) * 32;

    const int a_row = (lane & 7) + ((lane >> 3) & 1) * 8;
    const int a_kh  = (lane >> 4) * 8;
    const int b_row = (lane & 7) + ((lane >> 4) & 1) * 8;
    const int b_kh  = ((lane >> 3) & 1) * 8;

    float acc[4][4][4];
    #pragma unroll
    for (int i = 0; i < 4; i++)
        #pragma unroll
        for (int j = 0; j < 4; j++)
            #pragma unroll
            for (int q = 0; q < 4; q++) acc[i][j][q] = 0.f;

    const int lr_lo = tid >> 2;
    const int lc    = tid & 3;
    auto issue_loads = [&](int c, int buf) {
        const int k0 = c * BKg;
        const uint32_t sbuf = sb + buf * STGSZ;
        #pragma unroll
        for (int i = 0; i < 6; i++) {
            const int tensor = i >> 1;
            const int r = ((i & 1) << 6) + lr_lo;
            const __half* src;
            if (tensor == 0)      src = Ah + (size_t)(m0 + r) * K + k0 + lc * 8;
            else if (tensor == 1) src = Al + (size_t)(m0 + r) * K + k0 + lc * 8;
            else                  src = Bw + (size_t)(n0 + r) * K + k0 + lc * 8;
            uint32_t dst = sbuf + tensor * TSZ + r * ROWB + lc * 16;
            CP_ASYNC16(dst, src);
        }
        CP_COMMIT();
    };

    auto compute = [&](int buf) {
        const uint32_t sbuf = sb + buf * STGSZ;
        #pragma unroll
        for (int ks = 0; ks < 2; ks++) {
            uint32_t br[2][4];
            #pragma unroll
            for (int g = 0; g < 2; g++) {
                uint32_t addr = sbuf + 2 * TSZ +
                    (wn + g * 16 + b_row) * ROWB + (ks * 16 + b_kh) * 2;
                ldsm4(br[g], addr);
            }
            #pragma unroll
            for (int mt = 0; mt < 4; mt++) {
                uint32_t ah[4], al[4];
                uint32_t addrA = sbuf +
                    (wm + mt * 16 + a_row) * ROWB + (ks * 16 + a_kh) * 2;
                ldsm4(ah, addrA);
                ldsm4(al, addrA + TSZ);
                #pragma unroll
                for (int g = 0; g < 2; g++) {
                    #pragma unroll
                    for (int h8 = 0; h8 < 2; h8++) {
                        const int nt = g * 2 + h8;
                        mma_f16(acc[mt][nt], ah, br[g][h8*2], br[g][h8*2+1]);
                        mma_f16(acc[mt][nt], al, br[g][h8*2], br[g][h8*2+1]);
                    }
                }
            }
        }
    };

    issue_loads(0, 0);
    if (NC > 1) issue_loads(1, 1);
    for (int c = 0; c < NC; ++c) {
        const int buf = c % 3;
        if (c + 2 < NC) issue_loads(c + 2, (c + 2) % 3);
        const int rem = NC - 1 - c;
        if (rem >= 2)      CP_WAIT2();
        else if (rem == 1) CP_WAIT1();
        else               CP_WAIT0();
        __syncthreads();
        compute(buf);
        __syncthreads();
    }

    if (MODE == 0) {
        #pragma unroll
        for (int mt = 0; mt < 4; mt++) {
            const int m = m0 + wm + mt * 16 + (lane >> 2);
            #pragma unroll
            for (int nt = 0; nt < 4; nt++) {
                const int n = n0 + wn + nt * 8 + (lane & 3) * 2;
                float b0 = 0.f, b1 = 0.f;
                if (bias) { b0 = bias[n]; b1 = bias[n + 1]; }
                float2 v0, v1;
                v0.x = acc[mt][nt][0] + b0; v0.y = acc[mt][nt][1] + b1;
                v1.x = acc[mt][nt][2] + b0; v1.y = acc[mt][nt][3] + b1;
                *(float2*)&C[(size_t)m * N + n] = v0;
                *(float2*)&C[(size_t)(m + 8) * N + n] = v1;
            }
        }
    } else {
        const int slot = n0 >> 7;
        const int kvv = slot - NH;
        const int kvslot = slot - NH - NKV;
        #pragma unroll
        for (int mt = 0; mt < 4; mt++) {
            const int mrow = m0 + wm + mt * 16 + (lane >> 2);
            const int s0 = mrow & (SS - 1), bb0 = mrow >> 11;
            const int s1 = (mrow + 8) & (SS - 1), bb1 = (mrow + 8) >> 11;
            #pragma unroll
            for (int nt = 0; nt < 4; nt++) {
                const int n = n0 + wn + nt * 8 + (lane & 3) * 2;
                const int d = n & 127;
                float v0 = acc[mt][nt][0] + bias[n];
                float v1 = acc[mt][nt][1] + bias[n + 1];
                float v2 = acc[mt][nt][2] + bias[n];
                float v3 = acc[mt][nt][3] + bias[n + 1];
                if (slot < NH + NKV && d < ROT) {
                    float2 c0 = tab[s0 * (ROT/2) + (d >> 1)];
                    float o0 = v0 * c0.x - v1 * c0.y;
                    float o1 = v1 * c0.x + v0 * c0.y;
                    v0 = o0; v1 = o1;
                    float2 c1 = tab[s1 * (ROT/2) + (d >> 1)];
                    float o2 = v2 * c1.x - v3 * c1.y;
                    float o3 = v3 * c1.x + v2 * c1.y;
                    v2 = o2; v3 = o3;
                }
                if (slot < NH) {
                    float h0 = h_hi(v0), h1 = h_hi(v1);
                    float h2 = h_hi(v2), h3 = h_hi(v3);
                    size_t base0 = ((size_t)(bb0 * NH + slot) * SS + s0) * HD + d;
                    size_t base1 = ((size_t)(bb1 * NH + slot) * SS + s1) * HD + d;
                    *(uint32_t*)&Qh[base0] = pack_h2(h0, h1);
                    *(uint32_t*)&Ql[base0] = pack_h2(v0 - h0, v1 - h1);
                    *(uint32_t*)&Qh[base1] = pack_h2(h2, h3);
                    *(uint32_t*)&Ql[base1] = pack_h2(v2 - h2, v3 - h3);
                } else if (slot < NH + NKV) {
                    size_t base0 = ((size_t)(bb0 * NKV + kvv) * SS + s0) * HD + d;
                    size_t base1 = ((size_t)(bb1 * NKV + kvv) * SS + s1) * HD + d;
                    *(uint32_t*)&Kq[base0] = pack_h2(v0, v1);
                    *(uint32_t*)&Kq[base1] = pack_h2(v2, v3);
                } else {
                    size_t vb0 = ((size_t)(bb0 * NKV + kvslot) * HD + d) * SS + s0;
                    size_t vb1 = ((size_t)(bb1 * NKV + kvslot) * HD + d) * SS + s1;
                    Vt[vb0]      = __float2half_rn(v0);
                    Vt[vb0 + SS] = __float2half_rn(v1);
                    Vt[vb1]      = __float2half_rn(v2);
                    Vt[vb1 + SS] = __float2half_rn(v3);
                }
            }
        }
    }
}

// ---------------- HMMA flash attention (fp16, 2-term S, 2-term PV) -----------
#define AQ 128
#define AK 64
#define QR 272
#define VR 144
#define SQH (AQ*QR)            // 34816
#define SKH (AK*QR)            // 17408
#define SVH (HD*VR)            // 18432
#define STG (SKH + SVH)        // 35840
#define ASMEM (2*SQH + 3*STG)  // 177152

__global__ __launch_bounds__(256, 1) void attn_kernel(
    const __half* __restrict__ Qh_g, const __half* __restrict__ Ql_g,
    const __half* __restrict__ K_g, const __half* __restrict__ Vt_g,
    __half* __restrict__ Oh_g, __half* __restrict__ Ol_g)
{
    extern __shared__ char smem[];
    const uint32_t sb = smem_u32(smem);
    const int tid = threadIdx.x;
    const int wid = tid >> 5;
    const int lane = tid & 31;
    const int qt = blockIdx.x;
    const int h  = blockIdx.y;
    const int b  = blockIdx.z;
    const int kvh = h / (NH / NKV);
    const int qbase = qt * AQ;
    const int ktmax = 2 * qt + 1;

    const size_t qoff = ((size_t)(b * NH + h) * SS + qbase) * HD;
    const size_t koff = ((size_t)(b * NKV + kvh) * SS) * HD;
    const size_t voff = ((size_t)(b * NKV + kvh) * HD) * SS;

    const int a_row = (lane & 7) + ((lane >> 3) & 1) * 8;
    const int a_kh  = (lane >> 4) * 8;
    const int b_row = (lane & 7) + ((lane >> 4) & 1) * 8;
    const int b_kh  = ((lane >> 3) & 1) * 8;

    #pragma unroll
    for (int i = 0; i < 8; i++) {
        int flat = i * 256 + tid;
        int r = flat >> 4, u = flat & 15;
        *(uint4*)(smem + r * QR + u * 16) =
            *(const uint4*)(Qh_g + qoff + (size_t)r * HD + u * 8);
        *(uint4*)(smem + SQH + r * QR + u * 16) =
            *(const uint4*)(Ql_g + qoff + (size_t)r * HD + u * 8);
    }

    auto issue_kv = [&](int kt, int buf) {
        const int kbase = kt * AK;
        const uint32_t st = sb + 2 * SQH + buf * STG;
        #pragma unroll
        for (int i = 0; i < 4; i++) {     // K: 1024 x 16B
            int flat = i * 256 + tid;
            int r = flat >> 4, u = flat & 15;
            CP_ASYNC16(st + r * QR + u * 16,
                       K_g + koff + (size_t)(kbase + r) * HD + u * 8);
        }
        #pragma unroll
        for (int i = 0; i < 4; i++) {     // Vt: 1024 x 16B
            int flat = i * 256 + tid;
            int r = flat >> 3, u = flat & 7;
            CP_ASYNC16(st + SKH + r * VR + u * 16,
                       Vt_g + voff + (size_t)r * SS + kbase + u * 8);
        }
        CP_COMMIT();
    };

    float oacc[16][4];
    #pragma unroll
    for (int i = 0; i < 16; i++)
        #pragma unroll
        for (int j = 0; j < 4; j++) oacc[i][j] = 0.f;
    float m0 = -INFINITY, m1 = -INFINITY, l0 = 0.f, l1 = 0.f;
    const float scale = 0.08838834764831845f;
    const int row0 = qbase + wid * 16 + (lane >> 2);
    const int row1 = row0 + 8;

    issue_kv(0, 0);
    issue_kv(1, 1);

    for (int kt = 0; kt <= ktmax; ++kt) {
        const int buf = kt % 3;
        const int kbase = kt * AK;
        if (kt + 2 <= ktmax) issue_kv(kt + 2, (kt + 2) % 3);
        const int rem = ktmax - kt;
        if (rem >= 2)      CP_WAIT2();
        else if (rem == 1) CP_WAIT1();
        else               CP_WAIT0();
        __syncthreads();

        const uint32_t stk = sb + 2 * SQH + buf * STG;
        const uint32_t stv = stk + SKH;

        // ---- S = Q K^T (Q 2-term fp16 split, K single fp16) ----
        float sacc[8][4];
        #pragma unroll
        for (int i = 0; i < 8; i++)
            #pragma unroll
            for (int j = 0; j < 4; j++) sacc[i][j] = 0.f;
        #pragma unroll
        for (int ks = 0; ks < 8; ks++) {
            uint32_t bk[4][4];
            #pragma unroll
            for (int g = 0; g < 4; g++) {
                uint32_t addr = stk + (g * 16 + b_row) * QR + (ks * 16 + b_kh) * 2;
                ldsm4(bk[g], addr);
            }
            uint32_t qa_h[4], qa_l[4];
            uint32_t addrA = sb + (wid * 16 + a_row) * QR + (ks * 16 + a_kh) * 2;
            ldsm4(qa_h, addrA);
            ldsm4(qa_l, addrA + SQH);
            #pragma unroll
            for (int g = 0; g < 4; g++) {
                #pragma unroll
                for (int h8 = 0; h8 < 2; h8++) {
                    const int nt = g * 2 + h8;
                    mma_f16(sacc[nt], qa_h, bk[g][h8*2], bk[g][h8*2+1]);
                    mma_f16(sacc[nt], qa_l, bk[g][h8*2], bk[g][h8*2+1]);
                }
            }
        }

        const bool need_mask = (kbase + AK - 1) > (qbase + wid * 16);
        #pragma unroll
        for (int nt = 0; nt < 8; nt++) {
            int c0 = kbase + nt * 8 + (lane & 3) * 2;
            #pragma unroll
            for (int j = 0; j < 4; j++) sacc[nt][j] *= scale;
            if (need_mask) {
                if (c0     > row0) sacc[nt][0] = -INFINITY;
                if (c0 + 1 > row0) sacc[nt][1] = -INFINITY;
                if (c0     > row1) sacc[nt][2] = -INFINITY;
                if (c0 + 1 > row1) sacc[nt][3] = -INFINITY;
            }
        }

        float mx0 = -INFINITY, mx1 = -INFINITY;
        #pragma unroll
        for (int nt = 0; nt < 8; nt++) {
            mx0 = fmaxf(mx0, fmaxf(sacc[nt][0], sacc[nt][1]));
            mx1 = fmaxf(mx1, fmaxf(sacc[nt][2], sacc[nt][3]));
        }
        #pragma unroll
        for (int off = 1; off <= 2; off <<= 1) {
            mx0 = fmaxf(mx0, __shfl_xor_sync(0xffffffffu, mx0, off));
            mx1 = fmaxf(mx1, __shfl_xor_sync(0xffffffffu, mx1, off));
        }
        float nm0 = fmaxf(m0, mx0), nm1 = fmaxf(m1, mx1);
        float sum0 = 0.f, sum1 = 0.f;
        #pragma unroll
        for (int nt = 0; nt < 8; nt++) {
            sacc[nt][0] = __expf(sacc[nt][0] - nm0);
            sacc[nt][1] = __expf(sacc[nt][1] - nm0);
            sacc[nt][2] = __expf(sacc[nt][2] - nm1);
            sacc[nt][3] = __expf(sacc[nt][3] - nm1);
            sum0 += sacc[nt][0] + sacc[nt][1];
            sum1 += sacc[nt][2] + sacc[nt][3];
        }
        #pragma unroll
        for (int off = 1; off <= 2; off <<= 1) {
            sum0 += __shfl_xor_sync(0xffffffffu, sum0, off);
            sum1 += __shfl_xor_sync(0xffffffffu, sum1, off);
        }
        float al0 = __expf(m0 - nm0), al1 = __expf(m1 - nm1);
        l0 = l0 * al0 + sum0; l1 = l1 * al1 + sum1;
        m0 = nm0; m1 = nm1;
        #pragma unroll
        for (int nt = 0; nt < 16; nt++) {
            oacc[nt][0] *= al0; oacc[nt][1] *= al0;
            oacc[nt][2] *= al1; oacc[nt][3] *= al1;
        }

        // ---- O += P V^T (P 2-term fp16 split, V single fp16) ----
        #pragma unroll
        for (int ks2 = 0; ks2 < 4; ks2++) {
            float* e = sacc[2 * ks2];
            float* o = sacc[2 * ks2 + 1];
            float eh[4], oh[4];
            #pragma unroll
            for (int j = 0; j < 4; j++) { eh[j] = h_hi(e[j]); oh[j] = h_hi(o[j]); }
            uint32_t pa_h[4], pa_l[4];
            pa_h[0] = pack_h2(eh[0], eh[1]);
            pa_h[1] = pack_h2(eh[2], eh[3]);
            pa_h[2] = pack_h2(oh[0], oh[1]);
            pa_h[3] = pack_h2(oh[2], oh[3]);
            pa_l[0] = pack_h2(e[0] - eh[0], e[1] - eh[1]);
            pa_l[1] = pack_h2(e[2] - eh[2], e[3] - eh[3]);
            pa_l[2] = pack_h2(o[0] - oh[0], o[1] - oh[1]);
            pa_l[3] = pack_h2(o[2] - oh[2], o[3] - oh[3]);
            #pragma unroll
            for (int g = 0; g < 8; g++) {
                uint32_t vh[4];
                uint32_t addr = stv + (g * 16 + b_row) * VR + (ks2 * 16 + b_kh) * 2;
                ldsm4(vh, addr);
                #pragma unroll
                for (int h8 = 0; h8 < 2; h8++) {
                    const int nt = g * 2 + h8;
                    mma_f16(oacc[nt], pa_h, vh[h8*2], vh[h8*2+1]);
                    mma_f16(oacc[nt], pa_l, vh[h8*2], vh[h8*2+1]);
                }
            }
        }
        __syncthreads();
    }

    // ---- epilogue: O/l -> fp16 hi/lo A-buffers for the Wo GEMM ----
    const float il0 = 1.f / l0, il1 = 1.f / l1;
    #pragma unroll
    for (int nt = 0; nt < 16; nt++) {
        int d = nt * 8 + (lane & 3) * 2;
        size_t i0 = ((size_t)b * SS + row0) * H_DIM + h * HD + d;
        size_t i1 = ((size_t)b * SS + row1) * H_DIM + h * HD + d;
        float v0 = oacc[nt][0] * il0, v1 = oacc[nt][1] * il0;
        float v2 = oacc[nt][2] * il1, v3 = oacc[nt][3] * il1;
        float h0 = h_hi(v0), h1v = h_hi(v1), h2 = h_hi(v2), h3 = h_hi(v3);
        *(uint32_t*)&Oh_g[i0] = pack_h2(h0, h1v);
        *(uint32_t*)&Ol_g[i0] = pack_h2(v0 - h0, v1 - h1v);
        *(uint32_t*)&Oh_g[i1] = pack_h2(h2, h3);
        *(uint32_t*)&Ol_g[i1] = pack_h2(v2 - h2, v3 - h3);
    }
}

// ---------------- launcher ----------------
extern "C" void kernel_launch(void* const* d_in, const int* in_sizes, int n_in,
                              void* d_out, int out_size)
{
    const float* hidden = (const float*)d_in[0];
    const float* Wqkv = (const float*)d_in[2];
    const float* bqkv = (const float*)d_in[3];
    const float* Wo   = (const float*)d_in[4];
    float* out = (float*)d_out;

    float2 *ropetab;
    __half *w1, *w2, *ah, *al, *q_h, *q_l, *k1, *vt;
    cudaGetSymbolAddress((void**)&ropetab, g_rope);
    cudaGetSymbolAddress((void**)&w1, g_W1);
    cudaGetSymbolAddress((void**)&w2, g_W2);
    cudaGetSymbolAddress((void**)&ah, g_A_h);
    cudaGetSymbolAddress((void**)&al, g_A_l);
    cudaGetSymbolAddress((void**)&q_h, g_Qh);
    cudaGetSymbolAddress((void**)&q_l, g_Ql);
    cudaGetSymbolAddress((void**)&k1, g_K1);
    cudaGetSymbolAddress((void**)&vt, g_Vt);

    // prep
    {
        dim3 g1(QKV_DIM / 32, H_DIM / 32);
        transpose_f16_kernel<<<g1, 256>>>(Wqkv, w1, H_DIM, QKV_DIM);
        dim3 g2(H_DIM / 32, H_DIM / 32);
        transpose_f16_kernel<<<g2, 256>>>(Wo, w2, H_DIM, H_DIM);
        int nt = SS * (ROT/2);
        rope_table_kernel<<<(nt + 255) / 256, 256>>>(ropetab);
        int n4 = TOK * H_DIM / 4;
        split_f16_kernel<<<(n4 + 255) / 256, 256>>>((const float4*)hidden,
                                                    (__half2*)ah, (__half2*)al, n4);
    }
    // QKV GEMM fused with bias + RoPE + split scatter
    {
        cudaFuncSetAttribute(gemm_f16_kernel<1>,
                             cudaFuncAttributeMaxDynamicSharedMemorySize, GSMEM);
        dim3 grid(QKV_DIM / BNg, TOK / BMg);
        gemm_f16_kernel<1><<<grid, 256, GSMEM>>>(ah, al, w1, bqkv, nullptr,
                                                 TOK, QKV_DIM, H_DIM, ropetab,
                                                 q_h, q_l, k1, vt);
    }
    // HMMA flash attention
    {
        cudaFuncSetAttribute(attn_kernel,
                             cudaFuncAttributeMaxDynamicSharedMemorySize, ASMEM);
        dim3 grid(SS / AQ, NH, BB);
        attn_kernel<<<grid, 256, ASMEM>>>(q_h, q_l, k1, vt, ah, al);
    }
    // output GEMM
    {
        cudaFuncSetAttribute(gemm_f16_kernel<0>,
                             cudaFuncAttributeMaxDynamicSharedMemorySize, GSMEM);
        dim3 grid(H_DIM / BNg, TOK / BMg);
        gemm_f16_kernel<0><<<grid, 256, GSMEM>>>(ah, al, w2, nullptr, out,
                                                 TOK, H_DIM, H_DIM, nullptr,
                                                 nullptr, nullptr, nullptr, nullptr);
    }
}

// round 9
// speedup vs baseline: 4.6548x; 1.0566x over previous
#include <cuda_runtime.h>
#include <cuda_bf16.h>
#include <cuda_fp16.h>
#include <math.h>
#include <stdint.h>

// ---------------- problem constants ----------------
#define H_DIM 4096
#define NH 32
#define NKV 2
#define HD 128
#define ROT 64
#define BB 2
#define SS 2048
#define QKV_DIM ((NH + 2*NKV)*HD)   // 4608
#define TOK (BB*SS)                 // 4096

// scratch (allocation-free rule: device globals)
__device__ __half g_W1[(size_t)QKV_DIM * H_DIM];     // Wqkv^T fp16 [N][K]
__device__ __half g_W2[(size_t)H_DIM * H_DIM];       // Wo^T fp16 [N][K]
__device__ __half g_A_h[(size_t)TOK * H_DIM];
__device__ __half g_A_l[(size_t)TOK * H_DIM];
__device__ __half g_Qh[(size_t)TOK * NH * HD];
__device__ __half g_Ql[(size_t)TOK * NH * HD];
__device__ __half g_K1[(size_t)TOK * NKV * HD];
__device__ __half g_Vt[(size_t)TOK * NKV * HD];
__device__ float2 g_rope[SS * (ROT/2)];

// ---------------- PTX helpers ----------------
__device__ __forceinline__ uint32_t smem_u32(const void* p) {
    uint32_t a;
    asm("{ .reg .u64 t; cvta.to.shared.u64 t, %1; cvt.u32.u64 %0, t; }"
        : "=r"(a) : "l"(p));
    return a;
}
__device__ __forceinline__ void ldsm4(uint32_t* r, uint32_t addr) {
    asm volatile("ldmatrix.sync.aligned.m8n8.x4.shared.b16 {%0,%1,%2,%3}, [%4];"
                 : "=r"(r[0]), "=r"(r[1]), "=r"(r[2]), "=r"(r[3]) : "r"(addr));
}
__device__ __forceinline__ void mma_f16(float* d, const uint32_t* a,
                                        uint32_t b0, uint32_t b1) {
    asm volatile("mma.sync.aligned.m16n8k16.row.col.f32.f16.f16.f32 "
                 "{%0,%1,%2,%3}, {%4,%5,%6,%7}, {%8,%9}, {%0,%1,%2,%3};"
                 : "+f"(d[0]), "+f"(d[1]), "+f"(d[2]), "+f"(d[3])
                 : "r"(a[0]), "r"(a[1]), "r"(a[2]), "r"(a[3]), "r"(b0), "r"(b1));
}
__device__ __forceinline__ uint32_t pack_h2(float lo, float hi) {
    __half2 t = __floats2half2_rn(lo, hi);
    return *(uint32_t*)&t;
}
__device__ __forceinline__ float h_hi(float x) {
    return __half2float(__float2half_rn(x));
}
#define CP_ASYNC16(dst, src) \
    asm volatile("cp.async.cg.shared.global [%0], [%1], 16;" :: "r"(dst), "l"(src))
#define CP_COMMIT() asm volatile("cp.async.commit_group;" ::: "memory")
#define CP_WAIT1() asm volatile("cp.async.wait_group 1;" ::: "memory")
#define CP_WAIT0() asm volatile("cp.async.wait_group 0;" ::: "memory")

// ---------------- conversion kernels ----------------
__global__ void split_f16_kernel(const float4* __restrict__ x,
                                 __half2* __restrict__ h,
                                 __half2* __restrict__ l, int n4)
{
    int i = blockIdx.x * blockDim.x + threadIdx.x;
    if (i >= n4) return;
    float4 v = x[i];
    float h0 = h_hi(v.x), h1 = h_hi(v.y), h2 = h_hi(v.z), h3 = h_hi(v.w);
    h[2*i]   = __floats2half2_rn(h0, h1);
    h[2*i+1] = __floats2half2_rn(h2, h3);
    l[2*i]   = __floats2half2_rn(v.x - h0, v.y - h1);
    l[2*i+1] = __floats2half2_rn(v.z - h2, v.w - h3);
}

__global__ void transpose_f16_kernel(const float* __restrict__ W,
                                     __half* __restrict__ T, int K, int N)
{
    __shared__ float t[32][33];
    int n0 = blockIdx.x * 32, k0 = blockIdx.y * 32;
    int tx = threadIdx.x & 31, g = threadIdx.x >> 5;
    #pragma unroll
    for (int j = 0; j < 4; j++) {
        int ky = g * 4 + j;
        t[ky][tx] = W[(size_t)(k0 + ky) * N + n0 + tx];
    }
    __syncthreads();
    #pragma unroll
    for (int j = 0; j < 4; j++) {
        int ny = g * 4 + j;
        T[(size_t)(n0 + ny) * K + k0 + tx] = __float2half_rn(t[tx][ny]);
    }
}

__global__ void rope_table_kernel(float2* __restrict__ tab)
{
    int idx = blockIdx.x * blockDim.x + threadIdx.x;
    if (idx >= SS * (ROT/2)) return;
    int s = idx >> 5, i = idx & 31;
    float inv  = 1.0f / powf(10000.0f, (float)(2 * i) / (float)ROT);
    float freq = (float)s * inv;
    double fd = (double)freq;
    tab[idx] = make_float2((float)cos(fd), (float)sin(fd));
}

// ---------------- fp16 2-term HMMA GEMM (3-stage, 1 sync/chunk) --------------
#define BMg 128
#define BNg 128
#define BKg 32
#define ROWB 80
#define TSZ (128*ROWB)     // 10240
#define STGSZ (3*TSZ)      // 30720 (Ah, Al, W)
#define GSMEM (3*STGSZ)    // 92160 (3 stages)

template<int MODE>
__global__ __launch_bounds__(256, 2) void gemm_f16_kernel(
    const __half* __restrict__ Ah, const __half* __restrict__ Al,
    const __half* __restrict__ Bw,
    const float* __restrict__ bias, float* __restrict__ C,
    int M, int N, int K,
    const float2* __restrict__ tab,
    __half* __restrict__ Qh, __half* __restrict__ Ql,
    __half* __restrict__ Kq, __half* __restrict__ Vt)
{
    extern __shared__ char smem[];
    const uint32_t sb = smem_u32(smem);
    const int tid = threadIdx.x;
    const int wid = tid >> 5;
    const int lane = tid & 31;
    const int m0 = blockIdx.y * BMg;
    const int n0 = blockIdx.x * BNg;
    const int NC = K / BKg;

    const int wm = (wid >> 2) * 64;
    const int wn = (wid & 3) * 32;

    const int a_row = (lane & 7) + ((lane >> 3) & 1) * 8;
    const int a_kh  = (lane >> 4) * 8;
    const int b_row = (lane & 7) + ((lane >> 4) & 1) * 8;
    const int b_kh  = ((lane >> 3) & 1) * 8;

    float acc[4][4][4];
    #pragma unroll
    for (int i = 0; i < 4; i++)
        #pragma unroll
        for (int j = 0; j < 4; j++)
            #pragma unroll
            for (int q = 0; q < 4; q++) acc[i][j][q] = 0.f;

    const int lr_lo = tid >> 2;
    const int lc    = tid & 3;
    auto issue_loads = [&](int c, int buf) {
        const int k0 = c * BKg;
        const uint32_t sbuf = sb + buf * STGSZ;
        #pragma unroll
        for (int i = 0; i < 6; i++) {
            const int tensor = i >> 1;
            const int r = ((i & 1) << 6) + lr_lo;
            const __half* src;
            if (tensor == 0)      src = Ah + (size_t)(m0 + r) * K + k0 + lc * 8;
            else if (tensor == 1) src = Al + (size_t)(m0 + r) * K + k0 + lc * 8;
            else                  src = Bw + (size_t)(n0 + r) * K + k0 + lc * 8;
            uint32_t dst = sbuf + tensor * TSZ + r * ROWB + lc * 16;
            CP_ASYNC16(dst, src);
        }
        CP_COMMIT();
    };

    auto compute = [&](int buf) {
        const uint32_t sbuf = sb + buf * STGSZ;
        #pragma unroll
        for (int ks = 0; ks < 2; ks++) {
            uint32_t br[2][4];
            #pragma unroll
            for (int g = 0; g < 2; g++) {
                uint32_t addr = sbuf + 2 * TSZ +
                    (wn + g * 16 + b_row) * ROWB + (ks * 16 + b_kh) * 2;
                ldsm4(br[g], addr);
            }
            #pragma unroll
            for (int mt = 0; mt < 4; mt++) {
                uint32_t ah[4], al[4];
                uint32_t addrA = sbuf +
                    (wm + mt * 16 + a_row) * ROWB + (ks * 16 + a_kh) * 2;
                ldsm4(ah, addrA);
                ldsm4(al, addrA + TSZ);
                #pragma unroll
                for (int g = 0; g < 2; g++) {
                    #pragma unroll
                    for (int h8 = 0; h8 < 2; h8++) {
                        const int nt = g * 2 + h8;
                        mma_f16(acc[mt][nt], ah, br[g][h8*2], br[g][h8*2+1]);
                        mma_f16(acc[mt][nt], al, br[g][h8*2], br[g][h8*2+1]);
                    }
                }
            }
        }
    };

    // 3-stage pipeline, one barrier per chunk:
    // wait(stage c) -> sync -> issue(c+2) -> compute(c)
    issue_loads(0, 0);
    issue_loads(1, 1);
    for (int c = 0; c < NC; ++c) {
        if (c + 1 < NC) CP_WAIT1();
        else            CP_WAIT0();
        __syncthreads();
        if (c + 2 < NC) issue_loads(c + 2, (c + 2) % 3);
        compute(c % 3);
    }

    if (MODE == 0) {
        #pragma unroll
        for (int mt = 0; mt < 4; mt++) {
            const int m = m0 + wm + mt * 16 + (lane >> 2);
            #pragma unroll
            for (int nt = 0; nt < 4; nt++) {
                const int n = n0 + wn + nt * 8 + (lane & 3) * 2;
                float b0 = 0.f, b1 = 0.f;
                if (bias) { b0 = bias[n]; b1 = bias[n + 1]; }
                float2 v0, v1;
                v0.x = acc[mt][nt][0] + b0; v0.y = acc[mt][nt][1] + b1;
                v1.x = acc[mt][nt][2] + b0; v1.y = acc[mt][nt][3] + b1;
                *(float2*)&C[(size_t)m * N + n] = v0;
                *(float2*)&C[(size_t)(m + 8) * N + n] = v1;
            }
        }
    } else {
        const int slot = n0 >> 7;
        const int kvv = slot - NH;
        const int kvslot = slot - NH - NKV;
        #pragma unroll
        for (int mt = 0; mt < 4; mt++) {
            const int mrow = m0 + wm + mt * 16 + (lane >> 2);
            const int s0 = mrow & (SS - 1), bb0 = mrow >> 11;
            const int s1 = (mrow + 8) & (SS - 1), bb1 = (mrow + 8) >> 11;
            #pragma unroll
            for (int nt = 0; nt < 4; nt++) {
                const int n = n0 + wn + nt * 8 + (lane & 3) * 2;
                const int d = n & 127;
                float v0 = acc[mt][nt][0] + bias[n];
                float v1 = acc[mt][nt][1] + bias[n + 1];
                float v2 = acc[mt][nt][2] + bias[n];
                float v3 = acc[mt][nt][3] + bias[n + 1];
                if (slot < NH + NKV && d < ROT) {
                    float2 c0 = tab[s0 * (ROT/2) + (d >> 1)];
                    float o0 = v0 * c0.x - v1 * c0.y;
                    float o1 = v1 * c0.x + v0 * c0.y;
                    v0 = o0; v1 = o1;
                    float2 c1 = tab[s1 * (ROT/2) + (d >> 1)];
                    float o2 = v2 * c1.x - v3 * c1.y;
                    float o3 = v3 * c1.x + v2 * c1.y;
                    v2 = o2; v3 = o3;
                }
                if (slot < NH) {
                    float h0 = h_hi(v0), h1 = h_hi(v1);
                    float h2 = h_hi(v2), h3 = h_hi(v3);
                    size_t base0 = ((size_t)(bb0 * NH + slot) * SS + s0) * HD + d;
                    size_t base1 = ((size_t)(bb1 * NH + slot) * SS + s1) * HD + d;
                    *(uint32_t*)&Qh[base0] = pack_h2(h0, h1);
                    *(uint32_t*)&Ql[base0] = pack_h2(v0 - h0, v1 - h1);
                    *(uint32_t*)&Qh[base1] = pack_h2(h2, h3);
                    *(uint32_t*)&Ql[base1] = pack_h2(v2 - h2, v3 - h3);
                } else if (slot < NH + NKV) {
                    size_t base0 = ((size_t)(bb0 * NKV + kvv) * SS + s0) * HD + d;
                    size_t base1 = ((size_t)(bb1 * NKV + kvv) * SS + s1) * HD + d;
                    *(uint32_t*)&Kq[base0] = pack_h2(v0, v1);
                    *(uint32_t*)&Kq[base1] = pack_h2(v2, v3);
                } else {
                    size_t vb0 = ((size_t)(bb0 * NKV + kvslot) * HD + d) * SS + s0;
                    size_t vb1 = ((size_t)(bb1 * NKV + kvslot) * HD + d) * SS + s1;
                    Vt[vb0]      = __float2half_rn(v0);
                    Vt[vb0 + SS] = __float2half_rn(v1);
                    Vt[vb1]      = __float2half_rn(v2);
                    Vt[vb1 + SS] = __float2half_rn(v3);
                }
            }
        }
    }
}

// ---------------- HMMA flash attention (fp16; 2-term S, 1-term PV) -----------
#define AQ 128
#define AK 64
#define QR 272
#define VR 144
#define SQH (AQ*QR)            // 34816
#define SKH (AK*QR)            // 17408
#define SVH (HD*VR)            // 18432
#define STG (SKH + SVH)        // 35840
#define ASMEM (2*SQH + 3*STG)  // 177152

__global__ __launch_bounds__(256, 1) void attn_kernel(
    const __half* __restrict__ Qh_g, const __half* __restrict__ Ql_g,
    const __half* __restrict__ K_g, const __half* __restrict__ Vt_g,
    __half* __restrict__ Oh_g, __half* __restrict__ Ol_g)
{
    extern __shared__ char smem[];
    const uint32_t sb = smem_u32(smem);
    const int tid = threadIdx.x;
    const int wid = tid >> 5;
    const int lane = tid & 31;
    const int qt = gridDim.x - 1 - blockIdx.x;   // LPT: long CTAs first
    const int h  = blockIdx.y;
    const int b  = blockIdx.z;
    const int kvh = h / (NH / NKV);
    const int qbase = qt * AQ;
    const int ktmax = 2 * qt + 1;

    const size_t qoff = ((size_t)(b * NH + h) * SS + qbase) * HD;
    const size_t koff = ((size_t)(b * NKV + kvh) * SS) * HD;
    const size_t voff = ((size_t)(b * NKV + kvh) * HD) * SS;

    const int a_row = (lane & 7) + ((lane >> 3) & 1) * 8;
    const int a_kh  = (lane >> 4) * 8;
    const int b_row = (lane & 7) + ((lane >> 4) & 1) * 8;
    const int b_kh  = ((lane >> 3) & 1) * 8;

    #pragma unroll
    for (int i = 0; i < 8; i++) {
        int flat = i * 256 + tid;
        int r = flat >> 4, u = flat & 15;
        *(uint4*)(smem + r * QR + u * 16) =
            *(const uint4*)(Qh_g + qoff + (size_t)r * HD + u * 8);
        *(uint4*)(smem + SQH + r * QR + u * 16) =
            *(const uint4*)(Ql_g + qoff + (size_t)r * HD + u * 8);
    }

    auto issue_kv = [&](int kt, int buf) {
        const int kbase = kt * AK;
        const uint32_t st = sb + 2 * SQH + buf * STG;
        #pragma unroll
        for (int i = 0; i < 4; i++) {
            int flat = i * 256 + tid;
            int r = flat >> 4, u = flat & 15;
            CP_ASYNC16(st + r * QR + u * 16,
                       K_g + koff + (size_t)(kbase + r) * HD + u * 8);
        }
        #pragma unroll
        for (int i = 0; i < 4; i++) {
            int flat = i * 256 + tid;
            int r = flat >> 3, u = flat & 7;
            CP_ASYNC16(st + SKH + r * VR + u * 16,
                       Vt_g + voff + (size_t)r * SS + kbase + u * 8);
        }
        CP_COMMIT();
    };

    float oacc[16][4];
    #pragma unroll
    for (int i = 0; i < 16; i++)
        #pragma unroll
        for (int j = 0; j < 4; j++) oacc[i][j] = 0.f;
    float m0 = -INFINITY, m1 = -INFINITY, l0 = 0.f, l1 = 0.f;
    const float scale = 0.08838834764831845f;
    const int row0 = qbase + wid * 16 + (lane >> 2);
    const int row1 = row0 + 8;

    issue_kv(0, 0);
    issue_kv(1, 1);

    for (int kt = 0; kt <= ktmax; ++kt) {
        const int buf = kt % 3;
        const int kbase = kt * AK;
        if (kt + 1 <= ktmax) CP_WAIT1();
        else                 CP_WAIT0();
        __syncthreads();
        if (kt + 2 <= ktmax) issue_kv(kt + 2, (kt + 2) % 3);

        const uint32_t stk = sb + 2 * SQH + buf * STG;
        const uint32_t stv = stk + SKH;

        // ---- S = Q K^T (Q 2-term fp16 split, K single fp16) ----
        float sacc[8][4];
        #pragma unroll
        for (int i = 0; i < 8; i++)
            #pragma unroll
            for (int j = 0; j < 4; j++) sacc[i][j] = 0.f;
        #pragma unroll
        for (int ks = 0; ks < 8; ks++) {
            uint32_t bk[4][4];
            #pragma unroll
            for (int g = 0; g < 4; g++) {
                uint32_t addr = stk + (g * 16 + b_row) * QR + (ks * 16 + b_kh) * 2;
                ldsm4(bk[g], addr);
            }
            uint32_t qa_h[4], qa_l[4];
            uint32_t addrA = sb + (wid * 16 + a_row) * QR + (ks * 16 + a_kh) * 2;
            ldsm4(qa_h, addrA);
            ldsm4(qa_l, addrA + SQH);
            #pragma unroll
            for (int g = 0; g < 4; g++) {
                #pragma unroll
                for (int h8 = 0; h8 < 2; h8++) {
                    const int nt = g * 2 + h8;
                    mma_f16(sacc[nt], qa_h, bk[g][h8*2], bk[g][h8*2+1]);
                    mma_f16(sacc[nt], qa_l, bk[g][h8*2], bk[g][h8*2+1]);
                }
            }
        }

        const bool need_mask = (kbase + AK - 1) > (qbase + wid * 16);
        #pragma unroll
        for (int nt = 0; nt < 8; nt++) {
            int c0 = kbase + nt * 8 + (lane & 3) * 2;
            #pragma unroll
            for (int j = 0; j < 4; j++) sacc[nt][j] *= scale;
            if (need_mask) {
                if (c0     > row0) sacc[nt][0] = -INFINITY;
                if (c0 + 1 > row0) sacc[nt][1] = -INFINITY;
                if (c0     > row1) sacc[nt][2] = -INFINITY;
                if (c0 + 1 > row1) sacc[nt][3] = -INFINITY;
            }
        }

        float mx0 = -INFINITY, mx1 = -INFINITY;
        #pragma unroll
        for (int nt = 0; nt < 8; nt++) {
            mx0 = fmaxf(mx0, fmaxf(sacc[nt][0], sacc[nt][1]));
            mx1 = fmaxf(mx1, fmaxf(sacc[nt][2], sacc[nt][3]));
        }
        #pragma unroll
        for (int off = 1; off <= 2; off <<= 1) {
            mx0 = fmaxf(mx0, __shfl_xor_sync(0xffffffffu, mx0, off));
            mx1 = fmaxf(mx1, __shfl_xor_sync(0xffffffffu, mx1, off));
        }
        float nm0 = fmaxf(m0, mx0), nm1 = fmaxf(m1, mx1);
        float sum0 = 0.f, sum1 = 0.f;
        #pragma unroll
        for (int nt = 0; nt < 8; nt++) {
            sacc[nt][0] = __expf(sacc[nt][0] - nm0);
            sacc[nt][1] = __expf(sacc[nt][1] - nm0);
            sacc[nt][2] = __expf(sacc[nt][2] - nm1);
            sacc[nt][3] = __expf(sacc[nt][3] - nm1);
            sum0 += sacc[nt][0] + sacc[nt][1];
            sum1 += sacc[nt][2] + sacc[nt][3];
        }
        #pragma unroll
        for (int off = 1; off <= 2; off <<= 1) {
            sum0 += __shfl_xor_sync(0xffffffffu, sum0, off);
            sum1 += __shfl_xor_sync(0xffffffffu, sum1, off);
        }
        float al0 = __expf(m0 - nm0), al1 = __expf(m1 - nm1);
        l0 = l0 * al0 + sum0; l1 = l1 * al1 + sum1;
        m0 = nm0; m1 = nm1;
        #pragma unroll
        for (int nt = 0; nt < 16; nt++) {
            oacc[nt][0] *= al0; oacc[nt][1] *= al0;
            oacc[nt][2] *= al1; oacc[nt][3] *= al1;
        }

        // ---- O += P V^T (P single fp16) ----
        #pragma unroll
        for (int ks2 = 0; ks2 < 4; ks2++) {
            float* e = sacc[2 * ks2];
            float* o = sacc[2 * ks2 + 1];
            uint32_t pa[4];
            pa[0] = pack_h2(e[0], e[1]);
            pa[1] = pack_h2(e[2], e[3]);
            pa[2] = pack_h2(o[0], o[1]);
            pa[3] = pack_h2(o[2], o[3]);
            #pragma unroll
            for (int g = 0; g < 8; g++) {
                uint32_t vh[4];
                uint32_t addr = stv + (g * 16 + b_row) * VR + (ks2 * 16 + b_kh) * 2;
                ldsm4(vh, addr);
                #pragma unroll
                for (int h8 = 0; h8 < 2; h8++) {
                    const int nt = g * 2 + h8;
                    mma_f16(oacc[nt], pa, vh[h8*2], vh[h8*2+1]);
                }
            }
        }
    }

    // ---- epilogue: O/l -> fp16 hi/lo A-buffers for the Wo GEMM ----
    const float il0 = 1.f / l0, il1 = 1.f / l1;
    #pragma unroll
    for (int nt = 0; nt < 16; nt++) {
        int d = nt * 8 + (lane & 3) * 2;
        size_t i0 = ((size_t)b * SS + row0) * H_DIM + h * HD + d;
        size_t i1 = ((size_t)b * SS + row1) * H_DIM + h * HD + d;
        float v0 = oacc[nt][0] * il0, v1 = oacc[nt][1] * il0;
        float v2 = oacc[nt][2] * il1, v3 = oacc[nt][3] * il1;
        float h0 = h_hi(v0), h1v = h_hi(v1), h2 = h_hi(v2), h3 = h_hi(v3);
        *(uint32_t*)&Oh_g[i0] = pack_h2(h0, h1v);
        *(uint32_t*)&Ol_g[i0] = pack_h2(v0 - h0, v1 - h1v);
        *(uint32_t*)&Oh_g[i1] = pack_h2(h2, h3);
        *(uint32_t*)&Ol_g[i1] = pack_h2(v2 - h2, v3 - h3);
    }
}

// ---------------- launcher ----------------
extern "C" void kernel_launch(void* const* d_in, const int* in_sizes, int n_in,
                              void* d_out, int out_size)
{
    const float* hidden = (const float*)d_in[0];
    const float* Wqkv = (const float*)d_in[2];
    const float* bqkv = (const float*)d_in[3];
    const float* Wo   = (const float*)d_in[4];
    float* out = (float*)d_out;

    float2 *ropetab;
    __half *w1, *w2, *ah, *al, *q_h, *q_l, *k1, *vt;
    cudaGetSymbolAddress((void**)&ropetab, g_rope);
    cudaGetSymbolAddress((void**)&w1, g_W1);
    cudaGetSymbolAddress((void**)&w2, g_W2);
    cudaGetSymbolAddress((void**)&ah, g_A_h);
    cudaGetSymbolAddress((void**)&al, g_A_l);
    cudaGetSymbolAddress((void**)&q_h, g_Qh);
    cudaGetSymbolAddress((void**)&q_l, g_Ql);
    cudaGetSymbolAddress((void**)&k1, g_K1);
    cudaGetSymbolAddress((void**)&vt, g_Vt);

    // prep
    {
        dim3 g1(QKV_DIM / 32, H_DIM / 32);
        transpose_f16_kernel<<<g1, 256>>>(Wqkv, w1, H_DIM, QKV_DIM);
        dim3 g2(H_DIM / 32, H_DIM / 32);
        transpose_f16_kernel<<<g2, 256>>>(Wo, w2, H_DIM, H_DIM);
        int nt = SS * (ROT/2);
        rope_table_kernel<<<(nt + 255) / 256, 256>>>(ropetab);
        int n4 = TOK * H_DIM / 4;
        split_f16_kernel<<<(n4 + 255) / 256, 256>>>((const float4*)hidden,
                                                    (__half2*)ah, (__half2*)al, n4);
    }
    // QKV GEMM fused with bias + RoPE + split scatter
    {
        cudaFuncSetAttribute(gemm_f16_kernel<1>,
                             cudaFuncAttributeMaxDynamicSharedMemorySize, GSMEM);
        dim3 grid(QKV_DIM / BNg, TOK / BMg);
        gemm_f16_kernel<1><<<grid, 256, GSMEM>>>(ah, al, w1, bqkv, nullptr,
                                                 TOK, QKV_DIM, H_DIM, ropetab,
                                                 q_h, q_l, k1, vt);
    }
    // HMMA flash attention
    {
        cudaFuncSetAttribute(attn_kernel,
                             cudaFuncAttributeMaxDynamicSharedMemorySize, ASMEM);
        dim3 grid(SS / AQ, NH, BB);
        attn_kernel<<<grid, 256, ASMEM>>>(q_h, q_l, k1, vt, ah, al);
    }
    // output GEMM
    {
        cudaFuncSetAttribute(gemm_f16_kernel<0>,
                             cudaFuncAttributeMaxDynamicSharedMemorySize, GSMEM);
        dim3 grid(H_DIM / BNg, TOK / BMg);
        gemm_f16_kernel<0><<<grid, 256, GSMEM>>>(ah, al, w2, nullptr, out,
                                                 TOK, H_DIM, H_DIM, nullptr,
                                                 nullptr, nullptr, nullptr, nullptr);
    }
}